// round 12
// baseline (speedup 1.0000x reference)
#include <cuda_runtime.h>
#include <cuda_bf16.h>
#include <math.h>
#include <stdint.h>

#define BB 32
#define NPB 2048
#define NN 65536
#define EE 1048576
#define HH 768
#define NH 8
#define DHH 96
#define SCALE_V 0.10206207261596577f

// ---------------- unified fp32 scratch (zeroed once per launch) ----------------
#define O_QP     0
#define O_Q      24576
#define O_QP2    49152
#define O_T      73728
#define O_U      98304
#define O_CTX    294912
#define O_TMP1   319488
#define O_BMEAN  344064
#define O_AGG1   368640
#define O_AGG    393216
#define O_GATE   417792
#define O_FUSED  442368
#define O_WSUM   466944
#define O_MEANX  663552
#define O_NSQ    688128
#define O_MEANP  753664
#define O_PATH   802816
#define O_GRAPH  827392
#define O_COMB   851968
#define O_CSIM   925696
#define O_NUM    925952
#define O_QN     991488
#define O_C      991520
#define TOTALF   991552

__device__ float g_buf[TOTALF];
__device__ float g_scores[(size_t)NN*NH];
__device__ float g_mx[BB*NH], g_se[BB*NH];
__device__ int   g_first_edge[NN];
__device__ int   g_cand[BB*8];
__device__ int   g_cnt[BB];
__device__ __align__(16) __nv_bfloat16 g_Wt[(size_t)HH*HH];

// ---------------- helpers ----------------
__device__ __forceinline__ uint32_t smem_to_u32(const void* p) {
    uint32_t a;
    asm("{ .reg .u64 t; cvta.to.shared.u64 t, %1; cvt.u32.u64 %0, t; }" : "=r"(a) : "l"(p));
    return a;
}
__device__ __forceinline__ void ldmA(uint32_t* a, uint32_t addr) {
    asm volatile("ldmatrix.sync.aligned.m8n8.x4.shared.b16 {%0,%1,%2,%3}, [%4];"
                 : "=r"(a[0]), "=r"(a[1]), "=r"(a[2]), "=r"(a[3]) : "r"(addr));
}
__device__ __forceinline__ void ldmB(uint32_t* b, uint32_t addr) {
    asm volatile("ldmatrix.sync.aligned.m8n8.x2.trans.shared.b16 {%0,%1}, [%2];"
                 : "=r"(b[0]), "=r"(b[1]) : "r"(addr));
}
__device__ __forceinline__ void mma16816(float* c, const uint32_t* a, const uint32_t* b) {
    asm volatile("mma.sync.aligned.m16n8k16.row.col.f32.bf16.bf16.f32 "
                 "{%0,%1,%2,%3}, {%4,%5,%6,%7}, {%8,%9}, {%0,%1,%2,%3};"
                 : "+f"(c[0]), "+f"(c[1]), "+f"(c[2]), "+f"(c[3])
                 : "r"(a[0]), "r"(a[1]), "r"(a[2]), "r"(a[3]), "r"(b[0]), "r"(b[1]));
}

// ---------------- prep: zero scratch, init first_edge, build Wt (bf16, transposed) ----------------
__global__ void k_prep(const float* __restrict__ W) {
    int i = blockIdx.x * 256 + threadIdx.x;
    if (i < TOTALF) g_buf[i] = 0.f;
    if (i < NN) g_first_edge[i] = EE;
    if (i < HH * HH) {
        int n = i / HH, k = i % HH;
        g_Wt[(size_t)n * HH + k] = __float2bfloat16(W[(size_t)k * HH + n]);
    }
}

// ---------------- multi-descriptor split-K small GEMM ----------------
struct GDesc {
    const float* A; const float* B; const float* bias; float* C;
    int lda, ldb, ldc, transB, K, actA, nx, ky;
};
struct GPack { GDesc d[8]; };

__global__ void k_gskm(GPack p) {
    GDesc d = p.d[blockIdx.z];
    if ((int)blockIdx.x >= d.nx || (int)blockIdx.y >= d.ky) return;
    __shared__ float sA[32][129];
    __shared__ float sB[128][33];
    int t = threadIdx.x;
    int c0 = blockIdx.x * 32, k0 = blockIdx.y * 128;
    int kn = min(128, d.K - k0);
    for (int idx = t; idx < 32 * 128; idx += 256) {
        int m = idx >> 7, kk = idx & 127;
        float v = (kk < kn) ? d.A[(size_t)m * d.lda + k0 + kk] : 0.f;
        if (d.actA) v = fmaxf(v, 0.f);
        sA[m][kk] = v;
    }
    for (int idx = t; idx < 128 * 32; idx += 256) {
        int kk = idx >> 5, nn = idx & 31;
        float v = 0.f;
        if (kk < kn) v = d.transB ? d.B[(size_t)(c0 + nn) * d.ldb + k0 + kk]
                                  : d.B[(size_t)(k0 + kk) * d.ldb + c0 + nn];
        sB[kk][nn] = v;
    }
    __syncthreads();
    int g = t >> 5, tx = t & 31;
    float a0 = 0.f, a1 = 0.f, a2 = 0.f, a3 = 0.f;
#pragma unroll 8
    for (int kk = 0; kk < 128; kk++) {
        float bv = sB[kk][tx];
        a0 += sA[g][kk] * bv;
        a1 += sA[g + 8][kk] * bv;
        a2 += sA[g + 16][kk] * bv;
        a3 += sA[g + 24][kk] * bv;
    }
    float bb = (d.bias && blockIdx.y == 0) ? d.bias[c0 + tx] : 0.f;
    atomicAdd(&d.C[(size_t)(g     ) * d.ldc + c0 + tx], a0 + bb);
    atomicAdd(&d.C[(size_t)(g +  8) * d.ldc + c0 + tx], a1 + bb);
    atomicAdd(&d.C[(size_t)(g + 16) * d.ldc + c0 + tx], a2 + bb);
    atomicAdd(&d.C[(size_t)(g + 24) * d.ldc + c0 + tx], a3 + bb);
}

// ---------------- qp2 stats ----------------
__global__ void k_qstats(const float* __restrict__ bn) {
    int b = blockIdx.x, t = threadIdx.x;
    __shared__ float s1[256], s2[256];
    float a = 0.f, d = 0.f;
    for (int j = t; j < HH; j += 256) {
        float v = g_buf[O_QP2 + b * HH + j];
        a += v * v; d += v * bn[j];
    }
    s1[t] = a; s2[t] = d; __syncthreads();
    for (int o = 128; o > 0; o >>= 1) {
        if (t < o) { s1[t] += s1[t + o]; s2[t] += s2[t + o]; }
        __syncthreads();
    }
    if (t == 0) { g_buf[O_QN + b] = fmaxf(sqrtf(s1[0]), 1e-8f); g_buf[O_C + b] = s2[0]; }
}

// ---------------- per-node head scores + cosine numerator ----------------
__global__ void k_scores(const float* __restrict__ X) {
    __shared__ float sU[NH * HH];
    __shared__ float sT[HH];
    int b = blockIdx.x >> 4, sub = blockIdx.x & 15;
    for (int i = threadIdx.x; i < NH * HH; i += 256) sU[i] = g_buf[O_U + b * NH * HH + i];
    for (int i = threadIdx.x; i < HH; i += 256) sT[i] = g_buf[O_T + b * HH + i];
    __syncthreads();
    float cb = g_buf[O_C + b];
    int warp = threadIdx.x >> 5, lane = threadIdx.x & 31;
    int nodebase = b * NPB + sub * 128 + warp * 16;
    for (int w = 0; w < 16; w++) {
        int n = nodebase + w;
        const float* xr = X + (size_t)n * HH;
        float acc[9];
#pragma unroll
        for (int i = 0; i < 9; i++) acc[i] = 0.f;
        for (int cc = 0; cc < HH / 32; cc++) {
            int base = cc * 32 + lane;
            float xv = xr[base];
#pragma unroll
            for (int h = 0; h < 8; h++) acc[h] += xv * sU[h * HH + base];
            acc[8] += xv * sT[base];
        }
#pragma unroll
        for (int i = 0; i < 9; i++)
            for (int o = 16; o > 0; o >>= 1)
                acc[i] += __shfl_xor_sync(0xffffffffu, acc[i], o);
        if (lane == 0) {
#pragma unroll
            for (int h = 0; h < 8; h++) g_scores[(size_t)n * NH + h] = acc[h] * SCALE_V;
            g_buf[O_NUM + n] = acc[8] + cb;
        }
    }
}

// ---------------- HMMA bf16 GEMM: nsq += rowsum((X @ WtT + bn)^2) ----------------
// CTA 128(M) x 256(N), K=768 in 24 steps of 32; 16 warps as 4(M) x 4(N).
// rbase selects the row-half (launched twice on s1 for pipelined consumption).
#define A_PITCH 40
#define MM_SMEM (2 * (128 * A_PITCH * 2 + 256 * A_PITCH * 2))

__global__ __launch_bounds__(512, 1)
void k_mma_norm(const float* __restrict__ X, const float* __restrict__ bn, int rbase)
{
    extern __shared__ __nv_bfloat16 sm[];
    __nv_bfloat16* Abuf[2] = { sm, sm + 128 * A_PITCH };
    __nv_bfloat16* Bbuf[2] = { sm + 2 * 128 * A_PITCH, sm + 2 * 128 * A_PITCH + 256 * A_PITCH };
    int t = threadIdx.x, lane = t & 31, warp = t >> 5;
    int warp_m = warp & 3, warp_n = warp >> 2;
    int r0 = rbase + blockIdx.x * 128, c0 = blockIdx.y * 256;

    float acc[2][8][4];
#pragma unroll
    for (int mi = 0; mi < 2; mi++)
#pragma unroll
        for (int ni = 0; ni < 8; ni++)
#pragma unroll
            for (int r = 0; r < 4; r++) acc[mi][ni][r] = 0.f;

    int rowA = t >> 2, segA = t & 3;
    int rowB = t >> 1, segB = t & 1;
    const float* apA = X + (size_t)(r0 + rowA) * HH + segA * 8;
    const __nv_bfloat16* bpB = g_Wt + (size_t)(c0 + rowB) * HH + segB * 16;

    float4 pa0, pa1;
    uint4 pb0, pb1;
    pa0 = *(const float4*)apA; pa1 = *(const float4*)(apA + 4);
    pb0 = *(const uint4*)bpB;  pb1 = *(const uint4*)(bpB + 8);
    {
        __nv_bfloat162 h[4];
        h[0] = __floats2bfloat162_rn(pa0.x, pa0.y);
        h[1] = __floats2bfloat162_rn(pa0.z, pa0.w);
        h[2] = __floats2bfloat162_rn(pa1.x, pa1.y);
        h[3] = __floats2bfloat162_rn(pa1.z, pa1.w);
        *(uint4*)(Abuf[0] + rowA * A_PITCH + segA * 8) = *(uint4*)h;
        *(uint4*)(Bbuf[0] + rowB * A_PITCH + segB * 16) = pb0;
        *(uint4*)(Bbuf[0] + rowB * A_PITCH + segB * 16 + 8) = pb1;
    }
    __syncthreads();

    for (int ck = 0; ck < 24; ck++) {
        int cur = ck & 1, nxt = cur ^ 1;
        if (ck < 23) {
            int k0 = (ck + 1) * 32;
            pa0 = *(const float4*)(apA + k0); pa1 = *(const float4*)(apA + k0 + 4);
            pb0 = *(const uint4*)(bpB + k0);  pb1 = *(const uint4*)(bpB + k0 + 8);
        }
        uint32_t sa = smem_to_u32(Abuf[cur]);
        uint32_t sbm = smem_to_u32(Bbuf[cur]);
#pragma unroll
        for (int kk = 0; kk < 2; kk++) {
            uint32_t afr[2][4], bfr[8][2];
#pragma unroll
            for (int mi = 0; mi < 2; mi++) {
                int mrow = warp_m * 32 + mi * 16 + (lane & 15);
                ldmA(afr[mi], sa + (uint32_t)(mrow * A_PITCH + kk * 16 + (lane >> 4) * 8) * 2);
            }
#pragma unroll
            for (int ni = 0; ni < 8; ni++) {
                int nrow = warp_n * 64 + ni * 8 + (lane & 7);
                ldmB(bfr[ni], sbm + (uint32_t)(nrow * A_PITCH + kk * 16 + ((lane >> 3) & 1) * 8) * 2);
            }
#pragma unroll
            for (int mi = 0; mi < 2; mi++)
#pragma unroll
                for (int ni = 0; ni < 8; ni++)
                    mma16816(acc[mi][ni], afr[mi], bfr[ni]);
        }
        if (ck < 23) {
            __nv_bfloat162 h[4];
            h[0] = __floats2bfloat162_rn(pa0.x, pa0.y);
            h[1] = __floats2bfloat162_rn(pa0.z, pa0.w);
            h[2] = __floats2bfloat162_rn(pa1.x, pa1.y);
            h[3] = __floats2bfloat162_rn(pa1.z, pa1.w);
            *(uint4*)(Abuf[nxt] + rowA * A_PITCH + segA * 8) = *(uint4*)h;
            *(uint4*)(Bbuf[nxt] + rowB * A_PITCH + segB * 16) = pb0;
            *(uint4*)(Bbuf[nxt] + rowB * A_PITCH + segB * 16 + 8) = pb1;
        }
        __syncthreads();
    }

#pragma unroll
    for (int mi = 0; mi < 2; mi++) {
#pragma unroll
        for (int half = 0; half < 2; half++) {
            float s = 0.f;
#pragma unroll
            for (int ni = 0; ni < 8; ni++) {
                int col = c0 + warp_n * 64 + ni * 8 + (lane & 3) * 2;
                float v0 = acc[mi][ni][half * 2 + 0] + bn[col];
                float v1 = acc[mi][ni][half * 2 + 1] + bn[col + 1];
                s += v0 * v0 + v1 * v1;
            }
            s += __shfl_xor_sync(0xffffffffu, s, 1);
            s += __shfl_xor_sync(0xffffffffu, s, 2);
            if ((lane & 3) == 0) {
                int row = r0 + warp_m * 32 + mi * 16 + half * 8 + (lane >> 2);
                atomicAdd(&g_buf[O_NSQ + row], s);
            }
        }
    }
}

// ---------------- softmax stats per (b,h) ----------------
__global__ void k_smstats() {
    int b = blockIdx.x >> 3, h = blockIdx.x & 7;
    int t = threadIdx.x;
    __shared__ float sm[256];
    float m = -1e30f;
    for (int i = t; i < NPB; i += 256)
        m = fmaxf(m, g_scores[(size_t)(b * NPB + i) * NH + h]);
    sm[t] = m; __syncthreads();
    for (int o = 128; o > 0; o >>= 1) { if (t < o) sm[t] = fmaxf(sm[t], sm[t + o]); __syncthreads(); }
    float mx = sm[0]; __syncthreads();
    float s = 0.f;
    for (int i = t; i < NPB; i += 256)
        s += expf(g_scores[(size_t)(b * NPB + i) * NH + h] - mx);
    sm[t] = s; __syncthreads();
    for (int o = 128; o > 0; o >>= 1) { if (t < o) sm[t] += sm[t + o]; __syncthreads(); }
    if (t == 0) { g_mx[b * NH + h] = mx; g_se[b * NH + h] = sm[0]; }
}

// ---------------- attention-weighted sums + mean(x), node-segmented ----------------
__global__ void k_wsum(const float* __restrict__ X) {
    int b = blockIdx.x, ch = blockIdx.y, seg = blockIdx.z;
    int t = threadIdx.x;                // 128
    __shared__ float sa[128][8];
    __shared__ float smx[8], sse[8];
    if (t < 8) { smx[t] = g_mx[b * NH + t]; sse[t] = 1.f / g_se[b * NH + t]; }
    __syncthreads();
    float acc[8];
#pragma unroll
    for (int h = 0; h < 8; h++) acc[h] = 0.f;
    float msum = 0.f;
    int col = ch * 128 + t;
    for (int n0 = seg * 512; n0 < seg * 512 + 512; n0 += 128) {
        size_t n = (size_t)(b * NPB + n0 + t);
#pragma unroll
        for (int h = 0; h < 8; h++)
            sa[t][h] = expf(g_scores[n * NH + h] - smx[h]) * sse[h];
        __syncthreads();
        for (int nn = 0; nn < 128; nn++) {
            float xv = X[(size_t)(b * NPB + n0 + nn) * HH + col];
            msum += xv;
#pragma unroll
            for (int h = 0; h < 8; h++) acc[h] += sa[nn][h] * xv;
        }
        __syncthreads();
    }
#pragma unroll
    for (int h = 0; h < 8; h++)
        atomicAdd(&g_buf[O_WSUM + (size_t)(b * NH + h) * HH + col], acc[h]);
    atomicAdd(&g_buf[O_MEANX + b * HH + col], msum * (1.f / (float)NPB));
}

// ---------------- first intra-graph outgoing edge ----------------
__global__ void k_edges(const int* __restrict__ ei, const int* __restrict__ bidx) {
    int e = blockIdx.x * blockDim.x + threadIdx.x;
    if (e < EE) {
        int s = ei[e], d = ei[EE + e];
        if (bidx[s] == bidx[d]) atomicMin(&g_first_edge[s], e);
    }
}

// ---------------- bf16-approx top-8 shortlist per batch (b0 = batch offset) ----------------
__global__ void k_top8(int b0) {
    int b = b0 + blockIdx.x, t = threadIdx.x;
    __shared__ float ssim[NPB];
    __shared__ float rv[256];
    __shared__ int ri[256];
    float qninv = 1.f / g_buf[O_QN + b];
    for (int i = t; i < NPB; i += 256) {
        int n = b * NPB + i;
        float nrm = fmaxf(sqrtf(g_buf[O_NSQ + n]), 1e-8f);
        ssim[i] = g_buf[O_NUM + n] * qninv / nrm;
    }
    __syncthreads();
    for (int k = 0; k < 8; k++) {
        float bv = -1e38f; int bi = 0x7fffffff;
        for (int i = t; i < NPB; i += 256) {
            float v = ssim[i];
            if (v > bv || (v == bv && i < bi)) { bv = v; bi = i; }
        }
        rv[t] = bv; ri[t] = bi; __syncthreads();
        for (int o = 128; o > 0; o >>= 1) {
            if (t < o) {
                if (rv[t + o] > rv[t] || (rv[t + o] == rv[t] && ri[t + o] < ri[t])) {
                    rv[t] = rv[t + o]; ri[t] = ri[t + o];
                }
            }
            __syncthreads();
        }
        if (t == 0) { g_cand[b * 8 + k] = b * NPB + ri[0]; ssim[ri[0]] = -1e38f; }
        __syncthreads();
    }
}

// ---------------- exact fp32 recheck, one CTA per batch (W streamed once) ----------------
__global__ void k_recheck3(const float* __restrict__ X, const float* __restrict__ W,
                           const float* __restrict__ bn, int b0)
{
    int b = b0 + blockIdx.x;
    int t = threadIdx.x;
    __shared__ float sx[8][HH];
    __shared__ float sr[256];
    for (int i = t; i < 8 * HH; i += 256) {
        int c = i / HH, k = i % HH;
        sx[c][k] = X[(size_t)g_cand[b * 8 + c] * HH + k];
    }
    __syncthreads();
    // thread t handles columns t, t+256, t+512
    float acc[8];
#pragma unroll
    for (int c = 0; c < 8; c++) acc[c] = 0.f;
    float v0[8], v1[8], v2[8];
#pragma unroll
    for (int c = 0; c < 8; c++) { v0[c] = bn[t]; v1[c] = bn[t + 256]; v2[c] = bn[t + 512]; }
#pragma unroll 4
    for (int k = 0; k < HH; k++) {
        float w0 = W[(size_t)k * HH + t];
        float w1 = W[(size_t)k * HH + t + 256];
        float w2 = W[(size_t)k * HH + t + 512];
#pragma unroll
        for (int c = 0; c < 8; c++) {
            float xv = sx[c][k];
            v0[c] += xv * w0;
            v1[c] += xv * w1;
            v2[c] += xv * w2;
        }
    }
#pragma unroll
    for (int c = 0; c < 8; c++)
        acc[c] = v0[c] * v0[c] + v1[c] * v1[c] + v2[c] * v2[c];
    // deterministic tree reduction per candidate
    for (int c = 0; c < 8; c++) {
        sr[t] = acc[c]; __syncthreads();
        for (int o = 128; o > 0; o >>= 1) {
            if (t < o) sr[t] += sr[t + o];
            __syncthreads();
        }
        if (t == 0) {
            float nrm = fmaxf(sqrtf(sr[0]), 1e-8f);
            int node = g_cand[b * 8 + c];
            g_buf[O_CSIM + b * 8 + c] = g_buf[O_NUM + node] / (g_buf[O_QN + b] * nrm);
        }
        __syncthreads();
    }
}

// ---------------- exact top-3 + path features (b0 = batch offset) ----------------
__global__ void k_pathfeat(const float* __restrict__ X, const int* __restrict__ ei, int b0) {
    int b = b0 + blockIdx.x, t = threadIdx.x;
    __shared__ int st[3], snb[3], sval[3];
    __shared__ int scnt;
    if (t == 0) {
        float v[8]; int ix[8]; bool used[8];
        for (int j = 0; j < 8; j++) {
            v[j] = g_buf[O_CSIM + b * 8 + j];
            ix[j] = g_cand[b * 8 + j];
            used[j] = false;
        }
        int c = 0;
        for (int k = 0; k < 3; k++) {
            int best = -1;
            for (int j = 0; j < 8; j++)
                if (!used[j] && (best < 0 || v[j] > v[best] ||
                                 (v[j] == v[best] && ix[j] < ix[best]))) best = j;
            used[best] = true;
            int node = ix[best];
            int fe = g_first_edge[node];
            int vl = (fe < EE) ? 1 : 0;
            int nbr = ei[EE + (vl ? fe : 0)];
            st[k] = node; snb[k] = nbr; sval[k] = vl; c += vl;
        }
        scnt = c; g_cnt[b] = c;
    }
    __syncthreads();
    float invc = 1.f / fmaxf((float)scnt, 1.f);
    for (int j = t; j < HH; j += 256) {
        float s = 0.f;
        for (int k = 0; k < 3; k++)
            if (sval[k])
                s += (X[(size_t)st[k] * HH + j] + X[(size_t)snb[k] * HH + j]) * 0.5f;
        g_buf[O_MEANP + b * HH + j] = s * invc;
    }
}

// ---------------- comb = [query, graph, path] ----------------
__global__ void k_comb(const float* __restrict__ query) {
    int i = blockIdx.x * 256 + threadIdx.x;
    int b = i / (3 * HH), j = i % (3 * HH);
    float v;
    if (j < HH)          v = query[b * HH + j];
    else if (j < 2 * HH) v = g_buf[O_GRAPH + b * HH + j - HH];
    else                 v = g_buf[O_PATH + b * HH + j - 2 * HH];
    g_buf[O_COMB + i] = v;
}

// ---------------- layernorm; mode 2: in *= sigmoid(in2); mode 3: select in/in2 by g_cnt ----------------
__global__ void k_ln(const float* __restrict__ in, const float* __restrict__ in2, int mode,
                     const float* __restrict__ gg, const float* __restrict__ bb,
                     float* __restrict__ out)
{
    int b = blockIdx.x, t = threadIdx.x;
    __shared__ float sx[HH];
    __shared__ float red[256];
    float s = 0.f;
    for (int j = t; j < HH; j += 256) {
        float v = in[b * HH + j];
        if (mode == 2) v *= 1.f / (1.f + expf(-in2[b * HH + j]));
        else if (mode == 3 && g_cnt[b] <= 0) v = in2[b * HH + j];
        sx[j] = v; s += v;
    }
    red[t] = s; __syncthreads();
    for (int o = 128; o > 0; o >>= 1) { if (t < o) red[t] += red[t + o]; __syncthreads(); }
    float m = red[0] * (1.f / HH); __syncthreads();
    float vs = 0.f;
    for (int j = t; j < HH; j += 256) { float d = sx[j] - m; vs += d * d; }
    red[t] = vs; __syncthreads();
    for (int o = 128; o > 0; o >>= 1) { if (t < o) red[t] += red[t + o]; __syncthreads(); }
    float inv = rsqrtf(red[0] * (1.f / HH) + 1e-5f);
    for (int j = t; j < HH; j += 256)
        out[b * HH + j] = (sx[j] - m) * inv * gg[j] + bb[j];
}

// ---------------- host ----------------
static float* addrf(const void* sym) {
    void* p = nullptr;
    cudaGetSymbolAddress(&p, sym);
    return (float*)p;
}

static GDesc mkdesc(const float* A, int lda, const float* B, int ldb, int transB,
                    const float* bias, float* C, int ldc, int Ncols, int K, int actA) {
    GDesc d;
    d.A = A; d.B = B; d.bias = bias; d.C = C;
    d.lda = lda; d.ldb = ldb; d.ldc = ldc; d.transB = transB;
    d.K = K; d.actA = actA;
    d.nx = (Ncols + 31) / 32; d.ky = (K + 127) / 128;
    return d;
}

extern "C" void kernel_launch(void* const* d_in, const int* in_sizes, int n_in,
                              void* d_out, int out_size)
{
    const float* query   = (const float*)d_in[0];
    const float* X       = (const float*)d_in[1];
    const int*   ei      = (const int*)  d_in[2];
    const int*   bidx    = (const int*)  d_in[3];
    const float* gr_wq   = (const float*)d_in[4];
    const float* gr_bq   = (const float*)d_in[5];
    const float* gr_aq_w = (const float*)d_in[6];
    const float* gr_aq_b = (const float*)d_in[7];
    const float* gr_ak_w = (const float*)d_in[8];
    // d_in[9] = gr_ak_b: per-(b,h) constant score shift, cancels in softmax
    const float* gr_av_w = (const float*)d_in[10];
    const float* gr_av_b = (const float*)d_in[11];
    const float* gr_ao_w = (const float*)d_in[12];
    const float* gr_ao_b = (const float*)d_in[13];
    const float* gr_ln_g = (const float*)d_in[14];
    const float* gr_ln_b = (const float*)d_in[15];
    const float* pf_wq   = (const float*)d_in[16];
    const float* pf_bq   = (const float*)d_in[17];
    const float* pf_wn   = (const float*)d_in[18];
    const float* pf_bn   = (const float*)d_in[19];
    const float* pf_a1_w = (const float*)d_in[20];
    const float* pf_a1_b = (const float*)d_in[21];
    const float* pf_a2_w = (const float*)d_in[22];
    const float* pf_a2_b = (const float*)d_in[23];
    const float* pf_ln_g = (const float*)d_in[24];
    const float* pf_ln_b = (const float*)d_in[25];
    const float* fu_gw   = (const float*)d_in[26];
    const float* fu_gb   = (const float*)d_in[27];
    const float* fu_pw   = (const float*)d_in[28];
    const float* fu_pb   = (const float*)d_in[29];
    const float* fu_ln_g = (const float*)d_in[30];
    const float* fu_ln_b = (const float*)d_in[31];
    float* out = (float*)d_out;

    float* G = addrf(g_buf);

    static cudaStream_t s1 = nullptr, s2 = nullptr;
    static cudaEvent_t evF = nullptr, evN1 = nullptr, evN2 = nullptr, evE = nullptr;
    if (!s1) {
        cudaStreamCreateWithFlags(&s1, cudaStreamNonBlocking);
        cudaStreamCreateWithFlags(&s2, cudaStreamNonBlocking);
        cudaEventCreateWithFlags(&evF, cudaEventDisableTiming);
        cudaEventCreateWithFlags(&evN1, cudaEventDisableTiming);
        cudaEventCreateWithFlags(&evN2, cudaEventDisableTiming);
        cudaEventCreateWithFlags(&evE, cudaEventDisableTiming);
        cudaFuncSetAttribute(k_mma_norm, cudaFuncAttributeMaxDynamicSharedMemorySize, MM_SMEM);
    }

    // prep on capture stream, then fork
    k_prep<<<(TOTALF + 255) / 256, 256>>>(pf_wn);
    cudaEventRecord(evF, 0);
    cudaStreamWaitEvent(s1, evF, 0);
    cudaStreamWaitEvent(s2, evF, 0);

    // s1: the norm GEMM in two row-halves (batches 0-15 then 16-31)
    k_mma_norm<<<dim3(256, 3), 512, MM_SMEM, s1>>>(X, pf_bn, 0);
    cudaEventRecord(evN1, s1);
    k_mma_norm<<<dim3(256, 3), 512, MM_SMEM, s1>>>(X, pf_bn, NN / 2);
    cudaEventRecord(evN2, s1);

    // s2: edge scan
    k_edges<<<EE / 256, 256, 0, s2>>>(ei, bidx);
    cudaEventRecord(evE, s2);

    // capture stream: attention chain (independent of nsq / edges)
    {
        GPack p;
        p.d[0] = mkdesc(query, HH, gr_wq, HH, 0, gr_bq, G + O_QP,  HH, HH, HH, 0);
        p.d[1] = mkdesc(query, HH, pf_wq, HH, 0, pf_bq, G + O_QP2, HH, HH, HH, 0);
        k_gskm<<<dim3(24, 6, 2), 256>>>(p);
    }
    k_qstats<<<BB, 256>>>(pf_bn);
    {
        GPack p;
        p.d[0] = mkdesc(G + O_QP,  HH, gr_aq_w, HH, 0, gr_aq_b, G + O_Q, HH, HH, HH, 0);
        p.d[1] = mkdesc(G + O_QP2, HH, pf_wn,   HH, 1, nullptr, G + O_T, HH, HH, HH, 0);
        k_gskm<<<dim3(24, 6, 2), 256>>>(p);
    }
    {
        GPack p;
        for (int h = 0; h < NH; h++)
            p.d[h] = mkdesc(G + O_Q + h * DHH, HH, gr_ak_w + h * DHH, HH, 1, nullptr,
                            G + O_U + h * HH, NH * HH, HH, DHH, 0);
        k_gskm<<<dim3(24, 1, 8), 256>>>(p);
    }
    k_scores<<<512, 256>>>(X);
    k_smstats<<<BB * NH, 256>>>();
    k_wsum<<<dim3(BB, 6, 4), 128>>>(X);
    {
        GPack p;
        for (int h = 0; h < NH; h++)
            p.d[h] = mkdesc(G + O_WSUM + h * HH, NH * HH, gr_av_w + h * DHH, HH, 0,
                            gr_av_b + h * DHH, G + O_CTX + h * DHH, HH, DHH, HH, 0);
        k_gskm<<<dim3(3, 6, 8), 256>>>(p);
    }
    {
        GPack p;
        p.d[0] = mkdesc(G + O_CTX, HH, gr_ao_w, HH, 0, gr_ao_b, G + O_TMP1, HH, HH, HH, 0);
        p.d[1] = mkdesc(G + O_MEANX, HH, pf_wn, HH, 0, pf_bn, G + O_BMEAN, HH, HH, HH, 0);
        k_gskm<<<dim3(24, 6, 2), 256>>>(p);
    }
    k_ln<<<BB, 256>>>(G + O_TMP1, nullptr, 0, gr_ln_g, gr_ln_b, G + O_GRAPH);

    // first-half shortlist work overlaps the second norm half
    cudaStreamWaitEvent(0, evN1, 0);
    k_top8<<<16, 256>>>(0);
    k_recheck3<<<16, 256>>>(X, pf_wn, pf_bn, 0);
    cudaStreamWaitEvent(0, evE, 0);
    k_pathfeat<<<16, 256>>>(X, ei, 0);

    // second half after the full norm completes
    cudaStreamWaitEvent(0, evN2, 0);
    k_top8<<<16, 256>>>(16);
    k_recheck3<<<16, 256>>>(X, pf_wn, pf_bn, 16);
    k_pathfeat<<<16, 256>>>(X, ei, 16);

    {
        GPack p;
        p.d[0] = mkdesc(G + O_MEANP, HH, pf_a1_w, HH, 0, pf_a1_b, G + O_AGG1, HH, HH, HH, 0);
        k_gskm<<<dim3(24, 6, 1), 256>>>(p);
    }
    {
        GPack p;
        p.d[0] = mkdesc(G + O_AGG1, HH, pf_a2_w, HH, 0, pf_a2_b, G + O_AGG, HH, HH, HH, 1);
        k_gskm<<<dim3(24, 6, 1), 256>>>(p);
    }
    k_ln<<<BB, 256>>>(G + O_AGG, G + O_BMEAN, 3, pf_ln_g, pf_ln_b, G + O_PATH);

    // fusion
    k_comb<<<BB * 3 * HH / 256, 256>>>(query);
    {
        GPack p;
        p.d[0] = mkdesc(G + O_COMB, 3 * HH, fu_gw, HH, 0, fu_gb, G + O_GATE,  HH, HH, 3 * HH, 0);
        p.d[1] = mkdesc(G + O_COMB, 3 * HH, fu_pw, HH, 0, fu_pb, G + O_FUSED, HH, HH, 3 * HH, 0);
        k_gskm<<<dim3(24, 18, 2), 256>>>(p);
    }
    k_ln<<<BB, 256>>>(G + O_FUSED, G + O_GATE, 2, fu_ln_g, fu_ln_b, out);
}

// round 13
// speedup vs baseline: 1.1545x; 1.1545x over previous
#include <cuda_runtime.h>
#include <cuda_bf16.h>
#include <math.h>
#include <stdint.h>

#define BB 32
#define NPB 2048
#define NN 65536
#define EE 1048576
#define HH 768
#define NH 8
#define DHH 96
#define SCALE_V 0.10206207261596577f

// ---------------- unified fp32 scratch (zeroed once per launch) ----------------
#define O_QP     0
#define O_Q      24576
#define O_QP2    49152
#define O_T      73728
#define O_U      98304
#define O_CTX    294912
#define O_TMP1   319488
#define O_BMEAN  344064
#define O_AGG1   368640
#define O_AGG    393216
#define O_GATE   417792
#define O_FUSED  442368
#define O_WSUM   466944
#define O_MEANX  663552
#define O_NSQ    688128
#define O_MEANP  753664
#define O_PATH   802816
#define O_GRAPH  827392
#define O_COMB   851968
#define O_NUM    925952
#define O_QN     991488
#define O_C      991520
#define TOTALF   991552

__device__ float g_buf[TOTALF];
__device__ float g_scores[(size_t)NN*NH];
__device__ float g_mx[BB*NH], g_se[BB*NH];
__device__ float g_csim3[BB*8*3];
__device__ int   g_first_edge[NN];
__device__ int   g_cand[BB*8];
__device__ int   g_cnt[BB];
__device__ __align__(16) __nv_bfloat16 g_Wt[(size_t)HH*HH];

// ---------------- helpers ----------------
__device__ __forceinline__ uint32_t smem_to_u32(const void* p) {
    uint32_t a;
    asm("{ .reg .u64 t; cvta.to.shared.u64 t, %1; cvt.u32.u64 %0, t; }" : "=r"(a) : "l"(p));
    return a;
}
__device__ __forceinline__ void ldmA(uint32_t* a, uint32_t addr) {
    asm volatile("ldmatrix.sync.aligned.m8n8.x4.shared.b16 {%0,%1,%2,%3}, [%4];"
                 : "=r"(a[0]), "=r"(a[1]), "=r"(a[2]), "=r"(a[3]) : "r"(addr));
}
__device__ __forceinline__ void ldmB(uint32_t* b, uint32_t addr) {
    asm volatile("ldmatrix.sync.aligned.m8n8.x2.trans.shared.b16 {%0,%1}, [%2];"
                 : "=r"(b[0]), "=r"(b[1]) : "r"(addr));
}
__device__ __forceinline__ void mma16816(float* c, const uint32_t* a, const uint32_t* b) {
    asm volatile("mma.sync.aligned.m16n8k16.row.col.f32.bf16.bf16.f32 "
                 "{%0,%1,%2,%3}, {%4,%5,%6,%7}, {%8,%9}, {%0,%1,%2,%3};"
                 : "+f"(c[0]), "+f"(c[1]), "+f"(c[2]), "+f"(c[3])
                 : "r"(a[0]), "r"(a[1]), "r"(a[2]), "r"(a[3]), "r"(b[0]), "r"(b[1]));
}

// ---------------- prep: zero scratch, init first_edge, build Wt (bf16, transposed) ----------------
__global__ void k_prep(const float* __restrict__ W) {
    int i = blockIdx.x * 256 + threadIdx.x;
    if (i < TOTALF) g_buf[i] = 0.f;
    if (i < NN) g_first_edge[i] = EE;
    if (i < HH * HH) {
        int n = i / HH, k = i % HH;
        g_Wt[(size_t)n * HH + k] = __float2bfloat16(W[(size_t)k * HH + n]);
    }
}

// ---------------- multi-descriptor split-K small GEMM ----------------
struct GDesc {
    const float* A; const float* B; const float* bias; float* C;
    int lda, ldb, ldc, transB, K, actA, nx, ky;
};
struct GPack { GDesc d[8]; };

__global__ void k_gskm(GPack p) {
    GDesc d = p.d[blockIdx.z];
    if ((int)blockIdx.x >= d.nx || (int)blockIdx.y >= d.ky) return;
    __shared__ float sA[32][129];
    __shared__ float sB[128][33];
    int t = threadIdx.x;
    int c0 = blockIdx.x * 32, k0 = blockIdx.y * 128;
    int kn = min(128, d.K - k0);
    for (int idx = t; idx < 32 * 128; idx += 256) {
        int m = idx >> 7, kk = idx & 127;
        float v = (kk < kn) ? d.A[(size_t)m * d.lda + k0 + kk] : 0.f;
        if (d.actA) v = fmaxf(v, 0.f);
        sA[m][kk] = v;
    }
    for (int idx = t; idx < 128 * 32; idx += 256) {
        int kk = idx >> 5, nn = idx & 31;
        float v = 0.f;
        if (kk < kn) v = d.transB ? d.B[(size_t)(c0 + nn) * d.ldb + k0 + kk]
                                  : d.B[(size_t)(k0 + kk) * d.ldb + c0 + nn];
        sB[kk][nn] = v;
    }
    __syncthreads();
    int g = t >> 5, tx = t & 31;
    float a0 = 0.f, a1 = 0.f, a2 = 0.f, a3 = 0.f;
#pragma unroll 8
    for (int kk = 0; kk < 128; kk++) {
        float bv = sB[kk][tx];
        a0 += sA[g][kk] * bv;
        a1 += sA[g + 8][kk] * bv;
        a2 += sA[g + 16][kk] * bv;
        a3 += sA[g + 24][kk] * bv;
    }
    float bb = (d.bias && blockIdx.y == 0) ? d.bias[c0 + tx] : 0.f;
    atomicAdd(&d.C[(size_t)(g     ) * d.ldc + c0 + tx], a0 + bb);
    atomicAdd(&d.C[(size_t)(g +  8) * d.ldc + c0 + tx], a1 + bb);
    atomicAdd(&d.C[(size_t)(g + 16) * d.ldc + c0 + tx], a2 + bb);
    atomicAdd(&d.C[(size_t)(g + 24) * d.ldc + c0 + tx], a3 + bb);
}

// ---------------- qp2 stats ----------------
__global__ void k_qstats(const float* __restrict__ bn) {
    int b = blockIdx.x, t = threadIdx.x;
    __shared__ float s1[256], s2[256];
    float a = 0.f, d = 0.f;
    for (int j = t; j < HH; j += 256) {
        float v = g_buf[O_QP2 + b * HH + j];
        a += v * v; d += v * bn[j];
    }
    s1[t] = a; s2[t] = d; __syncthreads();
    for (int o = 128; o > 0; o >>= 1) {
        if (t < o) { s1[t] += s1[t + o]; s2[t] += s2[t + o]; }
        __syncthreads();
    }
    if (t == 0) { g_buf[O_QN + b] = fmaxf(sqrtf(s1[0]), 1e-8f); g_buf[O_C + b] = s2[0]; }
}

// ---------------- per-node head scores + cosine numerator ----------------
__global__ void k_scores(const float* __restrict__ X) {
    __shared__ float sU[NH * HH];
    __shared__ float sT[HH];
    int b = blockIdx.x >> 4, sub = blockIdx.x & 15;
    for (int i = threadIdx.x; i < NH * HH; i += 256) sU[i] = g_buf[O_U + b * NH * HH + i];
    for (int i = threadIdx.x; i < HH; i += 256) sT[i] = g_buf[O_T + b * HH + i];
    __syncthreads();
    float cb = g_buf[O_C + b];
    int warp = threadIdx.x >> 5, lane = threadIdx.x & 31;
    int nodebase = b * NPB + sub * 128 + warp * 16;
    for (int w = 0; w < 16; w++) {
        int n = nodebase + w;
        const float* xr = X + (size_t)n * HH;
        float acc[9];
#pragma unroll
        for (int i = 0; i < 9; i++) acc[i] = 0.f;
        for (int cc = 0; cc < HH / 32; cc++) {
            int base = cc * 32 + lane;
            float xv = xr[base];
#pragma unroll
            for (int h = 0; h < 8; h++) acc[h] += xv * sU[h * HH + base];
            acc[8] += xv * sT[base];
        }
#pragma unroll
        for (int i = 0; i < 9; i++)
            for (int o = 16; o > 0; o >>= 1)
                acc[i] += __shfl_xor_sync(0xffffffffu, acc[i], o);
        if (lane == 0) {
#pragma unroll
            for (int h = 0; h < 8; h++) g_scores[(size_t)n * NH + h] = acc[h] * SCALE_V;
            g_buf[O_NUM + n] = acc[8] + cb;
        }
    }
}

// ---------------- HMMA bf16 GEMM: nsq += rowsum((X @ WtT + bn)^2) ----------------
// CTA 128(M) x 256(N), K=768 in 24 steps of 32; 16 warps as 4(M) x 4(N).
#define A_PITCH 40
#define MM_SMEM (2 * (128 * A_PITCH * 2 + 256 * A_PITCH * 2))

__global__ __launch_bounds__(512, 1)
void k_mma_norm(const float* __restrict__ X, const float* __restrict__ bn)
{
    extern __shared__ __nv_bfloat16 sm[];
    __nv_bfloat16* Abuf[2] = { sm, sm + 128 * A_PITCH };
    __nv_bfloat16* Bbuf[2] = { sm + 2 * 128 * A_PITCH, sm + 2 * 128 * A_PITCH + 256 * A_PITCH };
    int t = threadIdx.x, lane = t & 31, warp = t >> 5;
    int warp_m = warp & 3, warp_n = warp >> 2;
    int r0 = blockIdx.x * 128, c0 = blockIdx.y * 256;

    float acc[2][8][4];
#pragma unroll
    for (int mi = 0; mi < 2; mi++)
#pragma unroll
        for (int ni = 0; ni < 8; ni++)
#pragma unroll
            for (int r = 0; r < 4; r++) acc[mi][ni][r] = 0.f;

    int rowA = t >> 2, segA = t & 3;
    int rowB = t >> 1, segB = t & 1;
    const float* apA = X + (size_t)(r0 + rowA) * HH + segA * 8;
    const __nv_bfloat16* bpB = g_Wt + (size_t)(c0 + rowB) * HH + segB * 16;

    float4 pa0, pa1;
    uint4 pb0, pb1;
    pa0 = *(const float4*)apA; pa1 = *(const float4*)(apA + 4);
    pb0 = *(const uint4*)bpB;  pb1 = *(const uint4*)(bpB + 8);
    {
        __nv_bfloat162 h[4];
        h[0] = __floats2bfloat162_rn(pa0.x, pa0.y);
        h[1] = __floats2bfloat162_rn(pa0.z, pa0.w);
        h[2] = __floats2bfloat162_rn(pa1.x, pa1.y);
        h[3] = __floats2bfloat162_rn(pa1.z, pa1.w);
        *(uint4*)(Abuf[0] + rowA * A_PITCH + segA * 8) = *(uint4*)h;
        *(uint4*)(Bbuf[0] + rowB * A_PITCH + segB * 16) = pb0;
        *(uint4*)(Bbuf[0] + rowB * A_PITCH + segB * 16 + 8) = pb1;
    }
    __syncthreads();

    for (int ck = 0; ck < 24; ck++) {
        int cur = ck & 1, nxt = cur ^ 1;
        if (ck < 23) {
            int k0 = (ck + 1) * 32;
            pa0 = *(const float4*)(apA + k0); pa1 = *(const float4*)(apA + k0 + 4);
            pb0 = *(const uint4*)(bpB + k0);  pb1 = *(const uint4*)(bpB + k0 + 8);
        }
        uint32_t sa = smem_to_u32(Abuf[cur]);
        uint32_t sbm = smem_to_u32(Bbuf[cur]);
#pragma unroll
        for (int kk = 0; kk < 2; kk++) {
            uint32_t afr[2][4], bfr[8][2];
#pragma unroll
            for (int mi = 0; mi < 2; mi++) {
                int mrow = warp_m * 32 + mi * 16 + (lane & 15);
                ldmA(afr[mi], sa + (uint32_t)(mrow * A_PITCH + kk * 16 + (lane >> 4) * 8) * 2);
            }
#pragma unroll
            for (int ni = 0; ni < 8; ni++) {
                int nrow = warp_n * 64 + ni * 8 + (lane & 7);
                ldmB(bfr[ni], sbm + (uint32_t)(nrow * A_PITCH + kk * 16 + ((lane >> 3) & 1) * 8) * 2);
            }
#pragma unroll
            for (int mi = 0; mi < 2; mi++)
#pragma unroll
                for (int ni = 0; ni < 8; ni++)
                    mma16816(acc[mi][ni], afr[mi], bfr[ni]);
        }
        if (ck < 23) {
            __nv_bfloat162 h[4];
            h[0] = __floats2bfloat162_rn(pa0.x, pa0.y);
            h[1] = __floats2bfloat162_rn(pa0.z, pa0.w);
            h[2] = __floats2bfloat162_rn(pa1.x, pa1.y);
            h[3] = __floats2bfloat162_rn(pa1.z, pa1.w);
            *(uint4*)(Abuf[nxt] + rowA * A_PITCH + segA * 8) = *(uint4*)h;
            *(uint4*)(Bbuf[nxt] + rowB * A_PITCH + segB * 16) = pb0;
            *(uint4*)(Bbuf[nxt] + rowB * A_PITCH + segB * 16 + 8) = pb1;
        }
        __syncthreads();
    }

#pragma unroll
    for (int mi = 0; mi < 2; mi++) {
#pragma unroll
        for (int half = 0; half < 2; half++) {
            float s = 0.f;
#pragma unroll
            for (int ni = 0; ni < 8; ni++) {
                int col = c0 + warp_n * 64 + ni * 8 + (lane & 3) * 2;
                float v0 = acc[mi][ni][half * 2 + 0] + bn[col];
                float v1 = acc[mi][ni][half * 2 + 1] + bn[col + 1];
                s += v0 * v0 + v1 * v1;
            }
            s += __shfl_xor_sync(0xffffffffu, s, 1);
            s += __shfl_xor_sync(0xffffffffu, s, 2);
            if ((lane & 3) == 0) {
                int row = r0 + warp_m * 32 + mi * 16 + half * 8 + (lane >> 2);
                atomicAdd(&g_buf[O_NSQ + row], s);
            }
        }
    }
}

// ---------------- softmax stats per (b,h) ----------------
__global__ void k_smstats() {
    int b = blockIdx.x >> 3, h = blockIdx.x & 7;
    int t = threadIdx.x;
    __shared__ float sm[256];
    float m = -1e30f;
    for (int i = t; i < NPB; i += 256)
        m = fmaxf(m, g_scores[(size_t)(b * NPB + i) * NH + h]);
    sm[t] = m; __syncthreads();
    for (int o = 128; o > 0; o >>= 1) { if (t < o) sm[t] = fmaxf(sm[t], sm[t + o]); __syncthreads(); }
    float mx = sm[0]; __syncthreads();
    float s = 0.f;
    for (int i = t; i < NPB; i += 256)
        s += expf(g_scores[(size_t)(b * NPB + i) * NH + h] - mx);
    sm[t] = s; __syncthreads();
    for (int o = 128; o > 0; o >>= 1) { if (t < o) sm[t] += sm[t + o]; __syncthreads(); }
    if (t == 0) { g_mx[b * NH + h] = mx; g_se[b * NH + h] = sm[0]; }
}

// ---------------- attention-weighted sums + mean(x), node-segmented ----------------
__global__ void k_wsum(const float* __restrict__ X) {
    int b = blockIdx.x, ch = blockIdx.y, seg = blockIdx.z;
    int t = threadIdx.x;                // 128
    __shared__ float sa[128][8];
    __shared__ float smx[8], sse[8];
    if (t < 8) { smx[t] = g_mx[b * NH + t]; sse[t] = 1.f / g_se[b * NH + t]; }
    __syncthreads();
    float acc[8];
#pragma unroll
    for (int h = 0; h < 8; h++) acc[h] = 0.f;
    float msum = 0.f;
    int col = ch * 128 + t;
    for (int n0 = seg * 512; n0 < seg * 512 + 512; n0 += 128) {
        size_t n = (size_t)(b * NPB + n0 + t);
#pragma unroll
        for (int h = 0; h < 8; h++)
            sa[t][h] = expf(g_scores[n * NH + h] - smx[h]) * sse[h];
        __syncthreads();
        for (int nn = 0; nn < 128; nn++) {
            float xv = X[(size_t)(b * NPB + n0 + nn) * HH + col];
            msum += xv;
#pragma unroll
            for (int h = 0; h < 8; h++) acc[h] += sa[nn][h] * xv;
        }
        __syncthreads();
    }
#pragma unroll
    for (int h = 0; h < 8; h++)
        atomicAdd(&g_buf[O_WSUM + (size_t)(b * NH + h) * HH + col], acc[h]);
    atomicAdd(&g_buf[O_MEANX + b * HH + col], msum * (1.f / (float)NPB));
}

// ---------------- first intra-graph outgoing edge ----------------
__global__ void k_edges(const int* __restrict__ ei, const int* __restrict__ bidx) {
    int e = blockIdx.x * blockDim.x + threadIdx.x;
    if (e < EE) {
        int s = ei[e], d = ei[EE + e];
        if (bidx[s] == bidx[d]) atomicMin(&g_first_edge[s], e);
    }
}

// ---------------- bf16-approx top-8 shortlist per batch ----------------
__global__ void k_top8() {
    int b = blockIdx.x, t = threadIdx.x;
    __shared__ float ssim[NPB];
    __shared__ float rv[256];
    __shared__ int ri[256];
    float qninv = 1.f / g_buf[O_QN + b];
    for (int i = t; i < NPB; i += 256) {
        int n = b * NPB + i;
        float nrm = fmaxf(sqrtf(g_buf[O_NSQ + n]), 1e-8f);
        ssim[i] = g_buf[O_NUM + n] * qninv / nrm;
    }
    __syncthreads();
    for (int k = 0; k < 8; k++) {
        float bv = -1e38f; int bi = 0x7fffffff;
        for (int i = t; i < NPB; i += 256) {
            float v = ssim[i];
            if (v > bv || (v == bv && i < bi)) { bv = v; bi = i; }
        }
        rv[t] = bv; ri[t] = bi; __syncthreads();
        for (int o = 128; o > 0; o >>= 1) {
            if (t < o) {
                if (rv[t + o] > rv[t] || (rv[t + o] == rv[t] && ri[t + o] < ri[t])) {
                    rv[t] = rv[t + o]; ri[t] = ri[t + o];
                }
            }
            __syncthreads();
        }
        if (t == 0) { g_cand[b * 8 + k] = b * NPB + ri[0]; ssim[ri[0]] = -1e38f; }
        __syncthreads();
    }
}

// ---------------- exact fp32 recheck, col-third partials (deterministic) ----------------
// grid (32, 3): blockIdx.x = batch, blockIdx.y = column third.
// Each CTA holds its batch's 8 candidate rows in smem and streams 1/3 of W once.
__global__ void k_recheck2(const float* __restrict__ X, const float* __restrict__ W,
                           const float* __restrict__ bn)
{
    int b = blockIdx.x, third = blockIdx.y;
    int t = threadIdx.x;
    int col = third * 256 + t;
    __shared__ float sx[8][HH];
    __shared__ float sr[256];
    for (int i = t; i < 8 * HH; i += 256) {
        int c = i / HH, k = i % HH;
        sx[c][k] = X[(size_t)g_cand[b * 8 + c] * HH + k];
    }
    __syncthreads();
    float v[8];
#pragma unroll
    for (int c = 0; c < 8; c++) v[c] = bn[col];
#pragma unroll 4
    for (int k = 0; k < HH; k++) {
        float w = W[(size_t)k * HH + col];
#pragma unroll
        for (int c = 0; c < 8; c++) v[c] += sx[c][k] * w;
    }
    // deterministic tree reduction of squares per candidate
    for (int c = 0; c < 8; c++) {
        sr[t] = v[c] * v[c]; __syncthreads();
        for (int o = 128; o > 0; o >>= 1) {
            if (t < o) sr[t] += sr[t + o];
            __syncthreads();
        }
        if (t == 0) g_csim3[(b * 8 + c) * 3 + third] = sr[0];
        __syncthreads();
    }
}

// ---------------- exact top-3 + path features ----------------
__global__ void k_pathfeat(const float* __restrict__ X, const int* __restrict__ ei) {
    int b = blockIdx.x, t = threadIdx.x;
    __shared__ int st[3], snb[3], sval[3];
    __shared__ int scnt;
    if (t == 0) {
        float v[8]; int ix[8]; bool used[8];
        float qninv = 1.f / g_buf[O_QN + b];
        for (int j = 0; j < 8; j++) {
            int node = g_cand[b * 8 + j];
            float nsq = g_csim3[(b * 8 + j) * 3 + 0]
                      + g_csim3[(b * 8 + j) * 3 + 1]
                      + g_csim3[(b * 8 + j) * 3 + 2];
            float nrm = fmaxf(sqrtf(nsq), 1e-8f);
            v[j] = g_buf[O_NUM + node] * qninv / nrm;
            ix[j] = node;
            used[j] = false;
        }
        int c = 0;
        for (int k = 0; k < 3; k++) {
            int best = -1;
            for (int j = 0; j < 8; j++)
                if (!used[j] && (best < 0 || v[j] > v[best] ||
                                 (v[j] == v[best] && ix[j] < ix[best]))) best = j;
            used[best] = true;
            int node = ix[best];
            int fe = g_first_edge[node];
            int vl = (fe < EE) ? 1 : 0;
            int nbr = ei[EE + (vl ? fe : 0)];
            st[k] = node; snb[k] = nbr; sval[k] = vl; c += vl;
        }
        scnt = c; g_cnt[b] = c;
    }
    __syncthreads();
    float invc = 1.f / fmaxf((float)scnt, 1.f);
    for (int j = t; j < HH; j += 256) {
        float s = 0.f;
        for (int k = 0; k < 3; k++)
            if (sval[k])
                s += (X[(size_t)st[k] * HH + j] + X[(size_t)snb[k] * HH + j]) * 0.5f;
        g_buf[O_MEANP + b * HH + j] = s * invc;
    }
}

// ---------------- comb = [query, graph, path] ----------------
__global__ void k_comb(const float* __restrict__ query) {
    int i = blockIdx.x * 256 + threadIdx.x;
    int b = i / (3 * HH), j = i % (3 * HH);
    float v;
    if (j < HH)          v = query[b * HH + j];
    else if (j < 2 * HH) v = g_buf[O_GRAPH + b * HH + j - HH];
    else                 v = g_buf[O_PATH + b * HH + j - 2 * HH];
    g_buf[O_COMB + i] = v;
}

// ---------------- layernorm; mode 2: in *= sigmoid(in2); mode 3: select in/in2 by g_cnt ----------------
__global__ void k_ln(const float* __restrict__ in, const float* __restrict__ in2, int mode,
                     const float* __restrict__ gg, const float* __restrict__ bb,
                     float* __restrict__ out)
{
    int b = blockIdx.x, t = threadIdx.x;
    __shared__ float sx[HH];
    __shared__ float red[256];
    float s = 0.f;
    for (int j = t; j < HH; j += 256) {
        float v = in[b * HH + j];
        if (mode == 2) v *= 1.f / (1.f + expf(-in2[b * HH + j]));
        else if (mode == 3 && g_cnt[b] <= 0) v = in2[b * HH + j];
        sx[j] = v; s += v;
    }
    red[t] = s; __syncthreads();
    for (int o = 128; o > 0; o >>= 1) { if (t < o) red[t] += red[t + o]; __syncthreads(); }
    float m = red[0] * (1.f / HH); __syncthreads();
    float vs = 0.f;
    for (int j = t; j < HH; j += 256) { float d = sx[j] - m; vs += d * d; }
    red[t] = vs; __syncthreads();
    for (int o = 128; o > 0; o >>= 1) { if (t < o) red[t] += red[t + o]; __syncthreads(); }
    float inv = rsqrtf(red[0] * (1.f / HH) + 1e-5f);
    for (int j = t; j < HH; j += 256)
        out[b * HH + j] = (sx[j] - m) * inv * gg[j] + bb[j];
}

// ---------------- host ----------------
static float* addrf(const void* sym) {
    void* p = nullptr;
    cudaGetSymbolAddress(&p, sym);
    return (float*)p;
}

static GDesc mkdesc(const float* A, int lda, const float* B, int ldb, int transB,
                    const float* bias, float* C, int ldc, int Ncols, int K, int actA) {
    GDesc d;
    d.A = A; d.B = B; d.bias = bias; d.C = C;
    d.lda = lda; d.ldb = ldb; d.ldc = ldc; d.transB = transB;
    d.K = K; d.actA = actA;
    d.nx = (Ncols + 31) / 32; d.ky = (K + 127) / 128;
    return d;
}

extern "C" void kernel_launch(void* const* d_in, const int* in_sizes, int n_in,
                              void* d_out, int out_size)
{
    const float* query   = (const float*)d_in[0];
    const float* X       = (const float*)d_in[1];
    const int*   ei      = (const int*)  d_in[2];
    const int*   bidx    = (const int*)  d_in[3];
    const float* gr_wq   = (const float*)d_in[4];
    const float* gr_bq   = (const float*)d_in[5];
    const float* gr_aq_w = (const float*)d_in[6];
    const float* gr_aq_b = (const float*)d_in[7];
    const float* gr_ak_w = (const float*)d_in[8];
    // d_in[9] = gr_ak_b: per-(b,h) constant score shift, cancels in softmax
    const float* gr_av_w = (const float*)d_in[10];
    const float* gr_av_b = (const float*)d_in[11];
    const float* gr_ao_w = (const float*)d_in[12];
    const float* gr_ao_b = (const float*)d_in[13];
    const float* gr_ln_g = (const float*)d_in[14];
    const float* gr_ln_b = (const float*)d_in[15];
    const float* pf_wq   = (const float*)d_in[16];
    const float* pf_bq   = (const float*)d_in[17];
    const float* pf_wn   = (const float*)d_in[18];
    const float* pf_bn   = (const float*)d_in[19];
    const float* pf_a1_w = (const float*)d_in[20];
    const float* pf_a1_b = (const float*)d_in[21];
    const float* pf_a2_w = (const float*)d_in[22];
    const float* pf_a2_b = (const float*)d_in[23];
    const float* pf_ln_g = (const float*)d_in[24];
    const float* pf_ln_b = (const float*)d_in[25];
    const float* fu_gw   = (const float*)d_in[26];
    const float* fu_gb   = (const float*)d_in[27];
    const float* fu_pw   = (const float*)d_in[28];
    const float* fu_pb   = (const float*)d_in[29];
    const float* fu_ln_g = (const float*)d_in[30];
    const float* fu_ln_b = (const float*)d_in[31];
    float* out = (float*)d_out;

    float* G = addrf(g_buf);

    static cudaStream_t s1 = nullptr, s2 = nullptr;
    static cudaEvent_t evF = nullptr, evN = nullptr, evE = nullptr;
    if (!s1) {
        cudaStreamCreateWithFlags(&s1, cudaStreamNonBlocking);
        cudaStreamCreateWithFlags(&s2, cudaStreamNonBlocking);
        cudaEventCreateWithFlags(&evF, cudaEventDisableTiming);
        cudaEventCreateWithFlags(&evN, cudaEventDisableTiming);
        cudaEventCreateWithFlags(&evE, cudaEventDisableTiming);
        cudaFuncSetAttribute(k_mma_norm, cudaFuncAttributeMaxDynamicSharedMemorySize, MM_SMEM);
    }

    // prep on capture stream, then fork
    k_prep<<<(TOTALF + 255) / 256, 256>>>(pf_wn);
    cudaEventRecord(evF, 0);
    cudaStreamWaitEvent(s1, evF, 0);
    cudaStreamWaitEvent(s2, evF, 0);

    // s1: the big norm GEMM (fp32 X, in-register bf16 cvt — R6 structure)
    k_mma_norm<<<dim3(NN / 128, HH / 256), 512, MM_SMEM, s1>>>(X, pf_bn);
    cudaEventRecord(evN, s1);

    // s2: edge scan
    k_edges<<<EE / 256, 256, 0, s2>>>(ei, bidx);
    cudaEventRecord(evE, s2);

    // capture stream: attention chain (independent of nsq / edges)
    {
        GPack p;
        p.d[0] = mkdesc(query, HH, gr_wq, HH, 0, gr_bq, G + O_QP,  HH, HH, HH, 0);
        p.d[1] = mkdesc(query, HH, pf_wq, HH, 0, pf_bq, G + O_QP2, HH, HH, HH, 0);
        k_gskm<<<dim3(24, 6, 2), 256>>>(p);
    }
    k_qstats<<<BB, 256>>>(pf_bn);
    {
        GPack p;
        p.d[0] = mkdesc(G + O_QP,  HH, gr_aq_w, HH, 0, gr_aq_b, G + O_Q, HH, HH, HH, 0);
        p.d[1] = mkdesc(G + O_QP2, HH, pf_wn,   HH, 1, nullptr, G + O_T, HH, HH, HH, 0);
        k_gskm<<<dim3(24, 6, 2), 256>>>(p);
    }
    {
        GPack p;
        for (int h = 0; h < NH; h++)
            p.d[h] = mkdesc(G + O_Q + h * DHH, HH, gr_ak_w + h * DHH, HH, 1, nullptr,
                            G + O_U + h * HH, NH * HH, HH, DHH, 0);
        k_gskm<<<dim3(24, 1, 8), 256>>>(p);
    }
    k_scores<<<512, 256>>>(X);
    k_smstats<<<BB * NH, 256>>>();
    k_wsum<<<dim3(BB, 6, 4), 128>>>(X);
    {
        GPack p;
        for (int h = 0; h < NH; h++)
            p.d[h] = mkdesc(G + O_WSUM + h * HH, NH * HH, gr_av_w + h * DHH, HH, 0,
                            gr_av_b + h * DHH, G + O_CTX + h * DHH, HH, DHH, HH, 0);
        k_gskm<<<dim3(3, 6, 8), 256>>>(p);
    }
    {
        GPack p;
        p.d[0] = mkdesc(G + O_CTX, HH, gr_ao_w, HH, 0, gr_ao_b, G + O_TMP1, HH, HH, HH, 0);
        p.d[1] = mkdesc(G + O_MEANX, HH, pf_wn, HH, 0, pf_bn, G + O_BMEAN, HH, HH, HH, 0);
        k_gskm<<<dim3(24, 6, 2), 256>>>(p);
    }
    k_ln<<<BB, 256>>>(G + O_TMP1, nullptr, 0, gr_ln_g, gr_ln_b, G + O_GRAPH);

    // join: paths need nsq (s1) and first_edge (s2)
    cudaStreamWaitEvent(0, evN, 0);
    k_top8<<<BB, 256>>>();
    k_recheck2<<<dim3(BB, 3), 256>>>(X, pf_wn, pf_bn);
    cudaStreamWaitEvent(0, evE, 0);
    k_pathfeat<<<BB, 256>>>(X, ei);
    {
        GPack p;
        p.d[0] = mkdesc(G + O_MEANP, HH, pf_a1_w, HH, 0, pf_a1_b, G + O_AGG1, HH, HH, HH, 0);
        k_gskm<<<dim3(24, 6, 1), 256>>>(p);
    }
    {
        GPack p;
        p.d[0] = mkdesc(G + O_AGG1, HH, pf_a2_w, HH, 0, pf_a2_b, G + O_AGG, HH, HH, HH, 1);
        k_gskm<<<dim3(24, 6, 1), 256>>>(p);
    }
    k_ln<<<BB, 256>>>(G + O_AGG, G + O_BMEAN, 3, pf_ln_g, pf_ln_b, G + O_PATH);

    // fusion
    k_comb<<<BB * 3 * HH / 256, 256>>>(query);
    {
        GPack p;
        p.d[0] = mkdesc(G + O_COMB, 3 * HH, fu_gw, HH, 0, fu_gb, G + O_GATE,  HH, HH, 3 * HH, 0);
        p.d[1] = mkdesc(G + O_COMB, 3 * HH, fu_pw, HH, 0, fu_pb, G + O_FUSED, HH, HH, 3 * HH, 0);
        k_gskm<<<dim3(24, 18, 2), 256>>>(p);
    }
    k_ln<<<BB, 256>>>(G + O_FUSED, G + O_GATE, 2, fu_ln_g, fu_ln_b, out);
}

// round 14
// speedup vs baseline: 1.9681x; 1.7047x over previous
#include <cuda_runtime.h>
#include <math.h>
#include <stdint.h>

#define BB 32
#define NPB 2048
#define NN 65536
#define EE 1048576
#define HH 768
#define NH 8
#define DHH 96
#define KC 48
#define SCALE_V 0.10206207261596577f

// ---------------- unified fp32 scratch (zeroed once per launch) ----------------
#define O_QP     0
#define O_Q      24576
#define O_QP2    49152
#define O_T      73728
#define O_U      98304
#define O_CTX    294912
#define O_TMP1   319488
#define O_BMEAN  344064
#define O_AGG1   368640
#define O_AGG    393216
#define O_GATE   417792
#define O_FUSED  442368
#define O_WSUM   466944
#define O_MEANX  663552
#define O_MEANP  753664
#define O_PATH   802816
#define O_GRAPH  827392
#define O_COMB   851968
#define O_NUM    925952
#define O_QN     991488
#define O_C      991520
#define TOTALF   991552

__device__ float g_buf[TOTALF];
__device__ float g_scores[(size_t)NN*NH];
__device__ float g_mx[BB*NH], g_se[BB*NH];
__device__ float g_csimp[BB*KC*3];
__device__ int   g_first_edge[NN];
__device__ int   g_cand[BB*KC];
__device__ int   g_cnt[BB];

// ---------------- prep: zero scratch, init first_edge ----------------
__global__ void k_prep() {
    int i = blockIdx.x * 256 + threadIdx.x;
    if (i < TOTALF) g_buf[i] = 0.f;
    if (i < NN) g_first_edge[i] = EE;
}

// ---------------- multi-descriptor split-K small GEMM ----------------
struct GDesc {
    const float* A; const float* B; const float* bias; float* C;
    int lda, ldb, ldc, transB, K, actA, nx, ky;
};
struct GPack { GDesc d[8]; };

__global__ void k_gskm(GPack p) {
    GDesc d = p.d[blockIdx.z];
    if ((int)blockIdx.x >= d.nx || (int)blockIdx.y >= d.ky) return;
    __shared__ float sA[32][129];
    __shared__ float sB[128][33];
    int t = threadIdx.x;
    int c0 = blockIdx.x * 32, k0 = blockIdx.y * 128;
    int kn = min(128, d.K - k0);
    for (int idx = t; idx < 32 * 128; idx += 256) {
        int m = idx >> 7, kk = idx & 127;
        float v = (kk < kn) ? d.A[(size_t)m * d.lda + k0 + kk] : 0.f;
        if (d.actA) v = fmaxf(v, 0.f);
        sA[m][kk] = v;
    }
    for (int idx = t; idx < 128 * 32; idx += 256) {
        int kk = idx >> 5, nn = idx & 31;
        float v = 0.f;
        if (kk < kn) v = d.transB ? d.B[(size_t)(c0 + nn) * d.ldb + k0 + kk]
                                  : d.B[(size_t)(k0 + kk) * d.ldb + c0 + nn];
        sB[kk][nn] = v;
    }
    __syncthreads();
    int g = t >> 5, tx = t & 31;
    float a0 = 0.f, a1 = 0.f, a2 = 0.f, a3 = 0.f;
#pragma unroll 8
    for (int kk = 0; kk < 128; kk++) {
        float bv = sB[kk][tx];
        a0 += sA[g][kk] * bv;
        a1 += sA[g + 8][kk] * bv;
        a2 += sA[g + 16][kk] * bv;
        a3 += sA[g + 24][kk] * bv;
    }
    float bb = (d.bias && blockIdx.y == 0) ? d.bias[c0 + tx] : 0.f;
    atomicAdd(&d.C[(size_t)(g     ) * d.ldc + c0 + tx], a0 + bb);
    atomicAdd(&d.C[(size_t)(g +  8) * d.ldc + c0 + tx], a1 + bb);
    atomicAdd(&d.C[(size_t)(g + 16) * d.ldc + c0 + tx], a2 + bb);
    atomicAdd(&d.C[(size_t)(g + 24) * d.ldc + c0 + tx], a3 + bb);
}

// ---------------- qp2 stats ----------------
__global__ void k_qstats(const float* __restrict__ bn) {
    int b = blockIdx.x, t = threadIdx.x;
    __shared__ float s1[256], s2[256];
    float a = 0.f, d = 0.f;
    for (int j = t; j < HH; j += 256) {
        float v = g_buf[O_QP2 + b * HH + j];
        a += v * v; d += v * bn[j];
    }
    s1[t] = a; s2[t] = d; __syncthreads();
    for (int o = 128; o > 0; o >>= 1) {
        if (t < o) { s1[t] += s1[t + o]; s2[t] += s2[t + o]; }
        __syncthreads();
    }
    if (t == 0) { g_buf[O_QN + b] = fmaxf(sqrtf(s1[0]), 1e-8f); g_buf[O_C + b] = s2[0]; }
}

// ---------------- per-node head scores + cosine numerator ----------------
__global__ void k_scores(const float* __restrict__ X) {
    __shared__ float sU[NH * HH];
    __shared__ float sT[HH];
    int b = blockIdx.x >> 4, sub = blockIdx.x & 15;
    for (int i = threadIdx.x; i < NH * HH; i += 256) sU[i] = g_buf[O_U + b * NH * HH + i];
    for (int i = threadIdx.x; i < HH; i += 256) sT[i] = g_buf[O_T + b * HH + i];
    __syncthreads();
    float cb = g_buf[O_C + b];
    int warp = threadIdx.x >> 5, lane = threadIdx.x & 31;
    int nodebase = b * NPB + sub * 128 + warp * 16;
    for (int w = 0; w < 16; w++) {
        int n = nodebase + w;
        const float* xr = X + (size_t)n * HH;
        float acc[9];
#pragma unroll
        for (int i = 0; i < 9; i++) acc[i] = 0.f;
        for (int cc = 0; cc < HH / 32; cc++) {
            int base = cc * 32 + lane;
            float xv = xr[base];
#pragma unroll
            for (int h = 0; h < 8; h++) acc[h] += xv * sU[h * HH + base];
            acc[8] += xv * sT[base];
        }
#pragma unroll
        for (int i = 0; i < 9; i++)
            for (int o = 16; o > 0; o >>= 1)
                acc[i] += __shfl_xor_sync(0xffffffffu, acc[i], o);
        if (lane == 0) {
#pragma unroll
            for (int h = 0; h < 8; h++) g_scores[(size_t)n * NH + h] = acc[h] * SCALE_V;
            g_buf[O_NUM + n] = acc[8] + cb;
        }
    }
}

// ---------------- softmax stats per (b,h) ----------------
__global__ void k_smstats() {
    int b = blockIdx.x >> 3, h = blockIdx.x & 7;
    int t = threadIdx.x;
    __shared__ float sm[256];
    float m = -1e30f;
    for (int i = t; i < NPB; i += 256)
        m = fmaxf(m, g_scores[(size_t)(b * NPB + i) * NH + h]);
    sm[t] = m; __syncthreads();
    for (int o = 128; o > 0; o >>= 1) { if (t < o) sm[t] = fmaxf(sm[t], sm[t + o]); __syncthreads(); }
    float mx = sm[0]; __syncthreads();
    float s = 0.f;
    for (int i = t; i < NPB; i += 256)
        s += expf(g_scores[(size_t)(b * NPB + i) * NH + h] - mx);
    sm[t] = s; __syncthreads();
    for (int o = 128; o > 0; o >>= 1) { if (t < o) sm[t] += sm[t + o]; __syncthreads(); }
    if (t == 0) { g_mx[b * NH + h] = mx; g_se[b * NH + h] = sm[0]; }
}

// ---------------- attention-weighted sums + mean(x), node-segmented ----------------
__global__ void k_wsum(const float* __restrict__ X) {
    int b = blockIdx.x, ch = blockIdx.y, seg = blockIdx.z;
    int t = threadIdx.x;                // 128
    __shared__ float sa[128][8];
    __shared__ float smx[8], sse[8];
    if (t < 8) { smx[t] = g_mx[b * NH + t]; sse[t] = 1.f / g_se[b * NH + t]; }
    __syncthreads();
    float acc[8];
#pragma unroll
    for (int h = 0; h < 8; h++) acc[h] = 0.f;
    float msum = 0.f;
    int col = ch * 128 + t;
    for (int n0 = seg * 512; n0 < seg * 512 + 512; n0 += 128) {
        size_t n = (size_t)(b * NPB + n0 + t);
#pragma unroll
        for (int h = 0; h < 8; h++)
            sa[t][h] = expf(g_scores[n * NH + h] - smx[h]) * sse[h];
        __syncthreads();
        for (int nn = 0; nn < 128; nn++) {
            float xv = X[(size_t)(b * NPB + n0 + nn) * HH + col];
            msum += xv;
#pragma unroll
            for (int h = 0; h < 8; h++) acc[h] += sa[nn][h] * xv;
        }
        __syncthreads();
    }
#pragma unroll
    for (int h = 0; h < 8; h++)
        atomicAdd(&g_buf[O_WSUM + (size_t)(b * NH + h) * HH + col], acc[h]);
    atomicAdd(&g_buf[O_MEANX + b * HH + col], msum * (1.f / (float)NPB));
}

// ---------------- first intra-graph outgoing edge ----------------
__global__ void k_edges(const int* __restrict__ ei, const int* __restrict__ bidx) {
    int e = blockIdx.x * blockDim.x + threadIdx.x;
    if (e < EE) {
        int s = ei[e], d = ei[EE + e];
        if (bidx[s] == bidx[d]) atomicMin(&g_first_edge[s], e);
    }
}

// ---------------- top-48 shortlist by exact numerator (norms concentrate ±2.5%) ----------------
__global__ void k_topnum() {
    int b = blockIdx.x, t = threadIdx.x;
    __shared__ float sv[NPB];
    __shared__ float rv[256];
    __shared__ int ri[256];
    for (int i = t; i < NPB; i += 256)
        sv[i] = g_buf[O_NUM + b * NPB + i];
    __syncthreads();
    for (int k = 0; k < KC; k++) {
        float bv = -1e38f; int bi = 0x7fffffff;
        for (int i = t; i < NPB; i += 256) {
            float v = sv[i];
            if (v > bv || (v == bv && i < bi)) { bv = v; bi = i; }
        }
        rv[t] = bv; ri[t] = bi; __syncthreads();
        for (int o = 128; o > 0; o >>= 1) {
            if (t < o) {
                if (rv[t + o] > rv[t] || (rv[t + o] == rv[t] && ri[t + o] < ri[t])) {
                    rv[t] = rv[t + o]; ri[t] = ri[t + o];
                }
            }
            __syncthreads();
        }
        if (t == 0) { g_cand[b * KC + k] = b * NPB + ri[0]; sv[ri[0]] = -1e38f; }
        __syncthreads();
    }
}

// ---------------- exact fp32 norm partials for the 48 candidates ----------------
// grid (32, 3, 6): batch x column-third x candidate-group-of-8. Deterministic.
__global__ void k_recheck48(const float* __restrict__ X, const float* __restrict__ W,
                            const float* __restrict__ bn)
{
    int b = blockIdx.x, third = blockIdx.y, grp = blockIdx.z;
    int t = threadIdx.x;
    int col = third * 256 + t;
    __shared__ float sx[8][HH];
    __shared__ float sr[256];
    for (int i = t; i < 8 * HH; i += 256) {
        int c = i / HH, k = i % HH;
        sx[c][k] = X[(size_t)g_cand[b * KC + grp * 8 + c] * HH + k];
    }
    __syncthreads();
    float v[8];
#pragma unroll
    for (int c = 0; c < 8; c++) v[c] = bn[col];
#pragma unroll 4
    for (int k = 0; k < HH; k++) {
        float w = W[(size_t)k * HH + col];
#pragma unroll
        for (int c = 0; c < 8; c++) v[c] += sx[c][k] * w;
    }
    for (int c = 0; c < 8; c++) {
        sr[t] = v[c] * v[c]; __syncthreads();
        for (int o = 128; o > 0; o >>= 1) {
            if (t < o) sr[t] += sr[t + o];
            __syncthreads();
        }
        if (t == 0) g_csimp[(b * KC + grp * 8 + c) * 3 + third] = sr[0];
        __syncthreads();
    }
}

// ---------------- exact top-3 over 48 candidates + path features ----------------
__global__ void k_pathfeat(const float* __restrict__ X, const int* __restrict__ ei) {
    int b = blockIdx.x, t = threadIdx.x;
    __shared__ int st[3], snb[3], sval[3];
    __shared__ int scnt;
    if (t == 0) {
        float v[KC]; int ix[KC]; bool used[KC];
        float qninv = 1.f / g_buf[O_QN + b];
        for (int j = 0; j < KC; j++) {
            int node = g_cand[b * KC + j];
            float nsq = g_csimp[(b * KC + j) * 3 + 0]
                      + g_csimp[(b * KC + j) * 3 + 1]
                      + g_csimp[(b * KC + j) * 3 + 2];
            float nrm = fmaxf(sqrtf(nsq), 1e-8f);
            v[j] = g_buf[O_NUM + node] * qninv / nrm;
            ix[j] = node;
            used[j] = false;
        }
        int c = 0;
        for (int k = 0; k < 3; k++) {
            int best = -1;
            for (int j = 0; j < KC; j++)
                if (!used[j] && (best < 0 || v[j] > v[best] ||
                                 (v[j] == v[best] && ix[j] < ix[best]))) best = j;
            used[best] = true;
            int node = ix[best];
            int fe = g_first_edge[node];
            int vl = (fe < EE) ? 1 : 0;
            int nbr = ei[EE + (vl ? fe : 0)];
            st[k] = node; snb[k] = nbr; sval[k] = vl; c += vl;
        }
        scnt = c; g_cnt[b] = c;
    }
    __syncthreads();
    float invc = 1.f / fmaxf((float)scnt, 1.f);
    for (int j = t; j < HH; j += 256) {
        float s = 0.f;
        for (int k = 0; k < 3; k++)
            if (sval[k])
                s += (X[(size_t)st[k] * HH + j] + X[(size_t)snb[k] * HH + j]) * 0.5f;
        g_buf[O_MEANP + b * HH + j] = s * invc;
    }
}

// ---------------- comb = [query, graph, path] ----------------
__global__ void k_comb(const float* __restrict__ query) {
    int i = blockIdx.x * 256 + threadIdx.x;
    int b = i / (3 * HH), j = i % (3 * HH);
    float v;
    if (j < HH)          v = query[b * HH + j];
    else if (j < 2 * HH) v = g_buf[O_GRAPH + b * HH + j - HH];
    else                 v = g_buf[O_PATH + b * HH + j - 2 * HH];
    g_buf[O_COMB + i] = v;
}

// ---------------- layernorm; mode 2: in *= sigmoid(in2); mode 3: select in/in2 by g_cnt ----------------
__global__ void k_ln(const float* __restrict__ in, const float* __restrict__ in2, int mode,
                     const float* __restrict__ gg, const float* __restrict__ bb,
                     float* __restrict__ out)
{
    int b = blockIdx.x, t = threadIdx.x;
    __shared__ float sx[HH];
    __shared__ float red[256];
    float s = 0.f;
    for (int j = t; j < HH; j += 256) {
        float v = in[b * HH + j];
        if (mode == 2) v *= 1.f / (1.f + expf(-in2[b * HH + j]));
        else if (mode == 3 && g_cnt[b] <= 0) v = in2[b * HH + j];
        sx[j] = v; s += v;
    }
    red[t] = s; __syncthreads();
    for (int o = 128; o > 0; o >>= 1) { if (t < o) red[t] += red[t + o]; __syncthreads(); }
    float m = red[0] * (1.f / HH); __syncthreads();
    float vs = 0.f;
    for (int j = t; j < HH; j += 256) { float d = sx[j] - m; vs += d * d; }
    red[t] = vs; __syncthreads();
    for (int o = 128; o > 0; o >>= 1) { if (t < o) red[t] += red[t + o]; __syncthreads(); }
    float inv = rsqrtf(red[0] * (1.f / HH) + 1e-5f);
    for (int j = t; j < HH; j += 256)
        out[b * HH + j] = (sx[j] - m) * inv * gg[j] + bb[j];
}

// ---------------- host ----------------
static float* addrf(const void* sym) {
    void* p = nullptr;
    cudaGetSymbolAddress(&p, sym);
    return (float*)p;
}

static GDesc mkdesc(const float* A, int lda, const float* B, int ldb, int transB,
                    const float* bias, float* C, int ldc, int Ncols, int K, int actA) {
    GDesc d;
    d.A = A; d.B = B; d.bias = bias; d.C = C;
    d.lda = lda; d.ldb = ldb; d.ldc = ldc; d.transB = transB;
    d.K = K; d.actA = actA;
    d.nx = (Ncols + 31) / 32; d.ky = (K + 127) / 128;
    return d;
}

extern "C" void kernel_launch(void* const* d_in, const int* in_sizes, int n_in,
                              void* d_out, int out_size)
{
    const float* query   = (const float*)d_in[0];
    const float* X       = (const float*)d_in[1];
    const int*   ei      = (const int*)  d_in[2];
    const int*   bidx    = (const int*)  d_in[3];
    const float* gr_wq   = (const float*)d_in[4];
    const float* gr_bq   = (const float*)d_in[5];
    const float* gr_aq_w = (const float*)d_in[6];
    const float* gr_aq_b = (const float*)d_in[7];
    const float* gr_ak_w = (const float*)d_in[8];
    // d_in[9] = gr_ak_b: per-(b,h) constant score shift, cancels in softmax
    const float* gr_av_w = (const float*)d_in[10];
    const float* gr_av_b = (const float*)d_in[11];
    const float* gr_ao_w = (const float*)d_in[12];
    const float* gr_ao_b = (const float*)d_in[13];
    const float* gr_ln_g = (const float*)d_in[14];
    const float* gr_ln_b = (const float*)d_in[15];
    const float* pf_wq   = (const float*)d_in[16];
    const float* pf_bq   = (const float*)d_in[17];
    const float* pf_wn   = (const float*)d_in[18];
    const float* pf_bn   = (const float*)d_in[19];
    const float* pf_a1_w = (const float*)d_in[20];
    const float* pf_a1_b = (const float*)d_in[21];
    const float* pf_a2_w = (const float*)d_in[22];
    const float* pf_a2_b = (const float*)d_in[23];
    const float* pf_ln_g = (const float*)d_in[24];
    const float* pf_ln_b = (const float*)d_in[25];
    const float* fu_gw   = (const float*)d_in[26];
    const float* fu_gb   = (const float*)d_in[27];
    const float* fu_pw   = (const float*)d_in[28];
    const float* fu_pb   = (const float*)d_in[29];
    const float* fu_ln_g = (const float*)d_in[30];
    const float* fu_ln_b = (const float*)d_in[31];
    float* out = (float*)d_out;

    float* G = addrf(g_buf);

    static cudaStream_t s1 = nullptr, s2 = nullptr;
    static cudaEvent_t evF = nullptr, evS = nullptr, evE = nullptr, evP = nullptr;
    if (!s1) {
        cudaStreamCreateWithFlags(&s1, cudaStreamNonBlocking);
        cudaStreamCreateWithFlags(&s2, cudaStreamNonBlocking);
        cudaEventCreateWithFlags(&evF, cudaEventDisableTiming);
        cudaEventCreateWithFlags(&evS, cudaEventDisableTiming);
        cudaEventCreateWithFlags(&evE, cudaEventDisableTiming);
        cudaEventCreateWithFlags(&evP, cudaEventDisableTiming);
    }

    // prep on capture stream, then fork edge scan
    k_prep<<<(TOTALF + 255) / 256, 256>>>();
    cudaEventRecord(evF, 0);
    cudaStreamWaitEvent(s2, evF, 0);
    k_edges<<<EE / 256, 256, 0, s2>>>(ei, bidx);
    cudaEventRecord(evE, s2);

    // main chain: projections -> scores
    {
        GPack p;
        p.d[0] = mkdesc(query, HH, gr_wq, HH, 0, gr_bq, G + O_QP,  HH, HH, HH, 0);
        p.d[1] = mkdesc(query, HH, pf_wq, HH, 0, pf_bq, G + O_QP2, HH, HH, HH, 0);
        k_gskm<<<dim3(24, 6, 2), 256>>>(p);
    }
    k_qstats<<<BB, 256>>>(pf_bn);
    {
        GPack p;
        p.d[0] = mkdesc(G + O_QP,  HH, gr_aq_w, HH, 0, gr_aq_b, G + O_Q, HH, HH, HH, 0);
        p.d[1] = mkdesc(G + O_QP2, HH, pf_wn,   HH, 1, nullptr, G + O_T, HH, HH, HH, 0);
        k_gskm<<<dim3(24, 6, 2), 256>>>(p);
    }
    {
        GPack p;
        for (int h = 0; h < NH; h++)
            p.d[h] = mkdesc(G + O_Q + h * DHH, HH, gr_ak_w + h * DHH, HH, 1, nullptr,
                            G + O_U + h * HH, NH * HH, HH, DHH, 0);
        k_gskm<<<dim3(24, 1, 8), 256>>>(p);
    }
    k_scores<<<512, 256>>>(X);
    cudaEventRecord(evS, 0);

    // s1: path branch (overlaps the attention rest)
    cudaStreamWaitEvent(s1, evS, 0);
    k_topnum<<<BB, 256, 0, s1>>>();
    k_recheck48<<<dim3(BB, 3, 6), 256, 0, s1>>>(X, pf_wn, pf_bn);
    cudaStreamWaitEvent(s1, evE, 0);
    k_pathfeat<<<BB, 256, 0, s1>>>(X, ei);
    {
        GPack p;
        p.d[0] = mkdesc(G + O_MEANP, HH, pf_a1_w, HH, 0, pf_a1_b, G + O_AGG1, HH, HH, HH, 0);
        k_gskm<<<dim3(24, 6, 1), 256, 0, s1>>>(p);
    }
    {
        GPack p;
        p.d[0] = mkdesc(G + O_AGG1, HH, pf_a2_w, HH, 0, pf_a2_b, G + O_AGG, HH, HH, HH, 1);
        k_gskm<<<dim3(24, 6, 1), 256, 0, s1>>>(p);
    }
    cudaEventRecord(evP, s1);

    // main: attention rest
    k_smstats<<<BB * NH, 256>>>();
    k_wsum<<<dim3(BB, 6, 4), 128>>>(X);
    {
        GPack p;
        for (int h = 0; h < NH; h++)
            p.d[h] = mkdesc(G + O_WSUM + h * HH, NH * HH, gr_av_w + h * DHH, HH, 0,
                            gr_av_b + h * DHH, G + O_CTX + h * DHH, HH, DHH, HH, 0);
        k_gskm<<<dim3(3, 6, 8), 256>>>(p);
    }
    {
        GPack p;
        p.d[0] = mkdesc(G + O_CTX, HH, gr_ao_w, HH, 0, gr_ao_b, G + O_TMP1, HH, HH, HH, 0);
        p.d[1] = mkdesc(G + O_MEANX, HH, pf_wn, HH, 0, pf_bn, G + O_BMEAN, HH, HH, HH, 0);
        k_gskm<<<dim3(24, 6, 2), 256>>>(p);
    }
    k_ln<<<BB, 256>>>(G + O_TMP1, nullptr, 0, gr_ln_g, gr_ln_b, G + O_GRAPH);

    // join: path-LN needs AGG (s1) + BMEAN + cnt
    cudaStreamWaitEvent(0, evP, 0);
    k_ln<<<BB, 256>>>(G + O_AGG, G + O_BMEAN, 3, pf_ln_g, pf_ln_b, G + O_PATH);

    // fusion
    k_comb<<<BB * 3 * HH / 256, 256>>>(query);
    {
        GPack p;
        p.d[0] = mkdesc(G + O_COMB, 3 * HH, fu_gw, HH, 0, fu_gb, G + O_GATE,  HH, HH, 3 * HH, 0);
        p.d[1] = mkdesc(G + O_COMB, 3 * HH, fu_pw, HH, 0, fu_pb, G + O_FUSED, HH, HH, 3 * HH, 0);
        k_gskm<<<dim3(24, 18, 2), 256>>>(p);
    }
    k_ln<<<BB, 256>>>(G + O_FUSED, G + O_GATE, 2, fu_ln_g, fu_ln_b, out);
}

// round 15
// speedup vs baseline: 2.1215x; 1.0779x over previous
#include <cuda_runtime.h>
#include <math.h>
#include <stdint.h>

#define BB 32
#define NPB 2048
#define NN 65536
#define EE 1048576
#define HH 768
#define NH 8
#define DHH 96
#define KC 48
#define SCALE_V 0.10206207261596577f

// ---------------- unified fp32 scratch (zeroed once per launch) ----------------
#define O_QP     0
#define O_Q      24576
#define O_QP2    49152
#define O_T      73728
#define O_U      98304
#define O_CTX    294912
#define O_TMP1   319488
#define O_BMEAN  344064
#define O_AGG1   368640
#define O_AGG    393216
#define O_GATE   417792
#define O_FUSED  442368
#define O_WSUM   466944
#define O_MEANX  663552
#define O_MEANP  753664
#define O_PATH   802816
#define O_GRAPH  827392
#define O_COMB   851968
#define O_NUM    925952
#define O_QN     991488
#define O_C      991520
#define TOTALF   991552

__device__ float g_buf[TOTALF];
__device__ float g_scores[(size_t)NN*NH];
__device__ float g_mx[BB*NH], g_se[BB*NH];
__device__ float g_csimp[BB*KC*3];
__device__ int   g_first_edge[NN];
__device__ int   g_cand[BB*KC];
__device__ int   g_cnt[BB];

// ---------------- prep: zero scratch, init first_edge ----------------
__global__ void k_prep() {
    int i = blockIdx.x * 256 + threadIdx.x;
    if (i < TOTALF) g_buf[i] = 0.f;
    if (i < NN) g_first_edge[i] = EE;
}

// ---------------- multi-descriptor split-K small GEMM ----------------
struct GDesc {
    const float* A; const float* B; const float* bias; float* C;
    int lda, ldb, ldc, transB, K, actA, nx, ky;
};
struct GPack { GDesc d[8]; };

__global__ void k_gskm(GPack p) {
    GDesc d = p.d[blockIdx.z];
    if ((int)blockIdx.x >= d.nx || (int)blockIdx.y >= d.ky) return;
    __shared__ float sA[32][129];
    __shared__ float sB[128][33];
    int t = threadIdx.x;
    int c0 = blockIdx.x * 32, k0 = blockIdx.y * 128;
    int kn = min(128, d.K - k0);
    for (int idx = t; idx < 32 * 128; idx += 256) {
        int m = idx >> 7, kk = idx & 127;
        float v = (kk < kn) ? d.A[(size_t)m * d.lda + k0 + kk] : 0.f;
        if (d.actA) v = fmaxf(v, 0.f);
        sA[m][kk] = v;
    }
    for (int idx = t; idx < 128 * 32; idx += 256) {
        int kk = idx >> 5, nn = idx & 31;
        float v = 0.f;
        if (kk < kn) v = d.transB ? d.B[(size_t)(c0 + nn) * d.ldb + k0 + kk]
                                  : d.B[(size_t)(k0 + kk) * d.ldb + c0 + nn];
        sB[kk][nn] = v;
    }
    __syncthreads();
    int g = t >> 5, tx = t & 31;
    float a0 = 0.f, a1 = 0.f, a2 = 0.f, a3 = 0.f;
#pragma unroll 8
    for (int kk = 0; kk < 128; kk++) {
        float bv = sB[kk][tx];
        a0 += sA[g][kk] * bv;
        a1 += sA[g + 8][kk] * bv;
        a2 += sA[g + 16][kk] * bv;
        a3 += sA[g + 24][kk] * bv;
    }
    float bb = (d.bias && blockIdx.y == 0) ? d.bias[c0 + tx] : 0.f;
    atomicAdd(&d.C[(size_t)(g     ) * d.ldc + c0 + tx], a0 + bb);
    atomicAdd(&d.C[(size_t)(g +  8) * d.ldc + c0 + tx], a1 + bb);
    atomicAdd(&d.C[(size_t)(g + 16) * d.ldc + c0 + tx], a2 + bb);
    atomicAdd(&d.C[(size_t)(g + 24) * d.ldc + c0 + tx], a3 + bb);
}

// ---------------- qp2 stats ----------------
__global__ void k_qstats(const float* __restrict__ bn) {
    int b = blockIdx.x, t = threadIdx.x;
    __shared__ float s1[256], s2[256];
    float a = 0.f, d = 0.f;
    for (int j = t; j < HH; j += 256) {
        float v = g_buf[O_QP2 + b * HH + j];
        a += v * v; d += v * bn[j];
    }
    s1[t] = a; s2[t] = d; __syncthreads();
    for (int o = 128; o > 0; o >>= 1) {
        if (t < o) { s1[t] += s1[t + o]; s2[t] += s2[t + o]; }
        __syncthreads();
    }
    if (t == 0) { g_buf[O_QN + b] = fmaxf(sqrtf(s1[0]), 1e-8f); g_buf[O_C + b] = s2[0]; }
}

// ---------------- per-node head scores + cosine numerator ----------------
__global__ void k_scores(const float* __restrict__ X) {
    __shared__ float sU[NH * HH];
    __shared__ float sT[HH];
    int b = blockIdx.x >> 4, sub = blockIdx.x & 15;
    for (int i = threadIdx.x; i < NH * HH; i += 256) sU[i] = g_buf[O_U + b * NH * HH + i];
    for (int i = threadIdx.x; i < HH; i += 256) sT[i] = g_buf[O_T + b * HH + i];
    __syncthreads();
    float cb = g_buf[O_C + b];
    int warp = threadIdx.x >> 5, lane = threadIdx.x & 31;
    int nodebase = b * NPB + sub * 128 + warp * 16;
    for (int w = 0; w < 16; w++) {
        int n = nodebase + w;
        const float* xr = X + (size_t)n * HH;
        float acc[9];
#pragma unroll
        for (int i = 0; i < 9; i++) acc[i] = 0.f;
#pragma unroll
        for (int cc = 0; cc < HH / 32; cc++) {
            int base = cc * 32 + lane;
            float xv = xr[base];
#pragma unroll
            for (int h = 0; h < 8; h++) acc[h] += xv * sU[h * HH + base];
            acc[8] += xv * sT[base];
        }
#pragma unroll
        for (int i = 0; i < 9; i++)
            for (int o = 16; o > 0; o >>= 1)
                acc[i] += __shfl_xor_sync(0xffffffffu, acc[i], o);
        if (lane == 0) {
#pragma unroll
            for (int h = 0; h < 8; h++) g_scores[(size_t)n * NH + h] = acc[h] * SCALE_V;
            g_buf[O_NUM + n] = acc[8] + cb;
        }
    }
}

// ---------------- softmax stats per (b,h) ----------------
__global__ void k_smstats() {
    int b = blockIdx.x >> 3, h = blockIdx.x & 7;
    int t = threadIdx.x;
    __shared__ float sm[256];
    float m = -1e30f;
    for (int i = t; i < NPB; i += 256)
        m = fmaxf(m, g_scores[(size_t)(b * NPB + i) * NH + h]);
    sm[t] = m; __syncthreads();
    for (int o = 128; o > 0; o >>= 1) { if (t < o) sm[t] = fmaxf(sm[t], sm[t + o]); __syncthreads(); }
    float mx = sm[0]; __syncthreads();
    float s = 0.f;
    for (int i = t; i < NPB; i += 256)
        s += expf(g_scores[(size_t)(b * NPB + i) * NH + h] - mx);
    sm[t] = s; __syncthreads();
    for (int o = 128; o > 0; o >>= 1) { if (t < o) sm[t] += sm[t + o]; __syncthreads(); }
    if (t == 0) { g_mx[b * NH + h] = mx; g_se[b * NH + h] = sm[0]; }
}

// ---------------- attention-weighted sums + mean(x): float4 per thread, 4x less LDS ----------------
// grid (BB, 16): each CTA handles one 128-node segment; 192 threads x 4 cols = 768 cols.
__global__ void k_wsum(const float* __restrict__ X) {
    int b = blockIdx.x, seg = blockIdx.y;
    int t = threadIdx.x;                // 192
    __shared__ float sa[128][8];
    __shared__ float smx[8], sse[8];
    if (t < 8) { smx[t] = g_mx[b * NH + t]; sse[t] = 1.f / g_se[b * NH + t]; }
    __syncthreads();
    int n0 = seg * 128;
    for (int idx = t; idx < 128 * 8; idx += 192) {
        int n = idx >> 3, h = idx & 7;
        sa[n][h] = expf(g_scores[(size_t)(b * NPB + n0 + n) * NH + h] - smx[h]) * sse[h];
    }
    __syncthreads();
    int col = t * 4;
    float acc[8][4];
#pragma unroll
    for (int h = 0; h < 8; h++)
#pragma unroll
        for (int j = 0; j < 4; j++) acc[h][j] = 0.f;
    float m0 = 0.f, m1 = 0.f, m2 = 0.f, m3 = 0.f;
#pragma unroll 4
    for (int nn = 0; nn < 128; nn++) {
        float4 xv = *(const float4*)(X + (size_t)(b * NPB + n0 + nn) * HH + col);
        m0 += xv.x; m1 += xv.y; m2 += xv.z; m3 += xv.w;
#pragma unroll
        for (int h = 0; h < 8; h++) {
            float a = sa[nn][h];
            acc[h][0] += a * xv.x;
            acc[h][1] += a * xv.y;
            acc[h][2] += a * xv.z;
            acc[h][3] += a * xv.w;
        }
    }
#pragma unroll
    for (int h = 0; h < 8; h++) {
        float* wp = &g_buf[O_WSUM + (size_t)(b * NH + h) * HH + col];
        atomicAdd(wp + 0, acc[h][0]);
        atomicAdd(wp + 1, acc[h][1]);
        atomicAdd(wp + 2, acc[h][2]);
        atomicAdd(wp + 3, acc[h][3]);
    }
    float inv = 1.f / (float)NPB;
    float* mp = &g_buf[O_MEANX + b * HH + col];
    atomicAdd(mp + 0, m0 * inv);
    atomicAdd(mp + 1, m1 * inv);
    atomicAdd(mp + 2, m2 * inv);
    atomicAdd(mp + 3, m3 * inv);
}

// ---------------- first intra-graph outgoing edge ----------------
__global__ void k_edges(const int* __restrict__ ei, const int* __restrict__ bidx) {
    int e = blockIdx.x * blockDim.x + threadIdx.x;
    if (e < EE) {
        int s = ei[e], d = ei[EE + e];
        if (bidx[s] == bidx[d]) atomicMin(&g_first_edge[s], e);
    }
}

// ---------------- top-48 shortlist by exact numerator (norms concentrate ±2.5%) ----------------
__global__ void k_topnum() {
    int b = blockIdx.x, t = threadIdx.x;
    __shared__ float sv[NPB];
    __shared__ float rv[256];
    __shared__ int ri[256];
    for (int i = t; i < NPB; i += 256)
        sv[i] = g_buf[O_NUM + b * NPB + i];
    __syncthreads();
    for (int k = 0; k < KC; k++) {
        float bv = -1e38f; int bi = 0x7fffffff;
        for (int i = t; i < NPB; i += 256) {
            float v = sv[i];
            if (v > bv || (v == bv && i < bi)) { bv = v; bi = i; }
        }
        rv[t] = bv; ri[t] = bi; __syncthreads();
        for (int o = 128; o > 0; o >>= 1) {
            if (t < o) {
                if (rv[t + o] > rv[t] || (rv[t + o] == rv[t] && ri[t + o] < ri[t])) {
                    rv[t] = rv[t + o]; ri[t] = ri[t + o];
                }
            }
            __syncthreads();
        }
        if (t == 0) { g_cand[b * KC + k] = b * NPB + ri[0]; sv[ri[0]] = -1e38f; }
        __syncthreads();
    }
}

// ---------------- exact fp32 norm partials for the 48 candidates ----------------
// grid (32, 3, 6): batch x column-third x candidate-group-of-8. Deterministic.
__global__ void k_recheck48(const float* __restrict__ X, const float* __restrict__ W,
                            const float* __restrict__ bn)
{
    int b = blockIdx.x, third = blockIdx.y, grp = blockIdx.z;
    int t = threadIdx.x;
    int col = third * 256 + t;
    __shared__ float sx[8][HH];
    __shared__ float sr[256];
    for (int i = t; i < 8 * HH; i += 256) {
        int c = i / HH, k = i % HH;
        sx[c][k] = X[(size_t)g_cand[b * KC + grp * 8 + c] * HH + k];
    }
    __syncthreads();
    float v[8];
#pragma unroll
    for (int c = 0; c < 8; c++) v[c] = bn[col];
#pragma unroll 4
    for (int k = 0; k < HH; k++) {
        float w = W[(size_t)k * HH + col];
#pragma unroll
        for (int c = 0; c < 8; c++) v[c] += sx[c][k] * w;
    }
    for (int c = 0; c < 8; c++) {
        sr[t] = v[c] * v[c]; __syncthreads();
        for (int o = 128; o > 0; o >>= 1) {
            if (t < o) sr[t] += sr[t + o];
            __syncthreads();
        }
        if (t == 0) g_csimp[(b * KC + grp * 8 + c) * 3 + third] = sr[0];
        __syncthreads();
    }
}

// ---------------- exact top-3 over 48 candidates + path features ----------------
__global__ void k_pathfeat(const float* __restrict__ X, const int* __restrict__ ei) {
    int b = blockIdx.x, t = threadIdx.x;
    __shared__ int st[3], snb[3], sval[3];
    __shared__ int scnt;
    if (t == 0) {
        float v[KC]; int ix[KC]; bool used[KC];
        float qninv = 1.f / g_buf[O_QN + b];
        for (int j = 0; j < KC; j++) {
            int node = g_cand[b * KC + j];
            float nsq = g_csimp[(b * KC + j) * 3 + 0]
                      + g_csimp[(b * KC + j) * 3 + 1]
                      + g_csimp[(b * KC + j) * 3 + 2];
            float nrm = fmaxf(sqrtf(nsq), 1e-8f);
            v[j] = g_buf[O_NUM + node] * qninv / nrm;
            ix[j] = node;
            used[j] = false;
        }
        int c = 0;
        for (int k = 0; k < 3; k++) {
            int best = -1;
            for (int j = 0; j < KC; j++)
                if (!used[j] && (best < 0 || v[j] > v[best] ||
                                 (v[j] == v[best] && ix[j] < ix[best]))) best = j;
            used[best] = true;
            int node = ix[best];
            int fe = g_first_edge[node];
            int vl = (fe < EE) ? 1 : 0;
            int nbr = ei[EE + (vl ? fe : 0)];
            st[k] = node; snb[k] = nbr; sval[k] = vl; c += vl;
        }
        scnt = c; g_cnt[b] = c;
    }
    __syncthreads();
    float invc = 1.f / fmaxf((float)scnt, 1.f);
    for (int j = t; j < HH; j += 256) {
        float s = 0.f;
        for (int k = 0; k < 3; k++)
            if (sval[k])
                s += (X[(size_t)st[k] * HH + j] + X[(size_t)snb[k] * HH + j]) * 0.5f;
        g_buf[O_MEANP + b * HH + j] = s * invc;
    }
}

// ---------------- comb = [query, graph, path] ----------------
__global__ void k_comb(const float* __restrict__ query) {
    int i = blockIdx.x * 256 + threadIdx.x;
    int b = i / (3 * HH), j = i % (3 * HH);
    float v;
    if (j < HH)          v = query[b * HH + j];
    else if (j < 2 * HH) v = g_buf[O_GRAPH + b * HH + j - HH];
    else                 v = g_buf[O_PATH + b * HH + j - 2 * HH];
    g_buf[O_COMB + i] = v;
}

// ---------------- layernorm; mode 2: in *= sigmoid(in2); mode 3: select in/in2 by g_cnt ----------------
__global__ void k_ln(const float* __restrict__ in, const float* __restrict__ in2, int mode,
                     const float* __restrict__ gg, const float* __restrict__ bb,
                     float* __restrict__ out)
{
    int b = blockIdx.x, t = threadIdx.x;
    __shared__ float sx[HH];
    __shared__ float red[256];
    float s = 0.f;
    for (int j = t; j < HH; j += 256) {
        float v = in[b * HH + j];
        if (mode == 2) v *= 1.f / (1.f + expf(-in2[b * HH + j]));
        else if (mode == 3 && g_cnt[b] <= 0) v = in2[b * HH + j];
        sx[j] = v; s += v;
    }
    red[t] = s; __syncthreads();
    for (int o = 128; o > 0; o >>= 1) { if (t < o) red[t] += red[t + o]; __syncthreads(); }
    float m = red[0] * (1.f / HH); __syncthreads();
    float vs = 0.f;
    for (int j = t; j < HH; j += 256) { float d = sx[j] - m; vs += d * d; }
    red[t] = vs; __syncthreads();
    for (int o = 128; o > 0; o >>= 1) { if (t < o) red[t] += red[t + o]; __syncthreads(); }
    float inv = rsqrtf(red[0] * (1.f / HH) + 1e-5f);
    for (int j = t; j < HH; j += 256)
        out[b * HH + j] = (sx[j] - m) * inv * gg[j] + bb[j];
}

// ---------------- host ----------------
static float* addrf(const void* sym) {
    void* p = nullptr;
    cudaGetSymbolAddress(&p, sym);
    return (float*)p;
}

static GDesc mkdesc(const float* A, int lda, const float* B, int ldb, int transB,
                    const float* bias, float* C, int ldc, int Ncols, int K, int actA) {
    GDesc d;
    d.A = A; d.B = B; d.bias = bias; d.C = C;
    d.lda = lda; d.ldb = ldb; d.ldc = ldc; d.transB = transB;
    d.K = K; d.actA = actA;
    d.nx = (Ncols + 31) / 32; d.ky = (K + 127) / 128;
    return d;
}

extern "C" void kernel_launch(void* const* d_in, const int* in_sizes, int n_in,
                              void* d_out, int out_size)
{
    const float* query   = (const float*)d_in[0];
    const float* X       = (const float*)d_in[1];
    const int*   ei      = (const int*)  d_in[2];
    const int*   bidx    = (const int*)  d_in[3];
    const float* gr_wq   = (const float*)d_in[4];
    const float* gr_bq   = (const float*)d_in[5];
    const float* gr_aq_w = (const float*)d_in[6];
    const float* gr_aq_b = (const float*)d_in[7];
    const float* gr_ak_w = (const float*)d_in[8];
    // d_in[9] = gr_ak_b: per-(b,h) constant score shift, cancels in softmax
    const float* gr_av_w = (const float*)d_in[10];
    const float* gr_av_b = (const float*)d_in[11];
    const float* gr_ao_w = (const float*)d_in[12];
    const float* gr_ao_b = (const float*)d_in[13];
    const float* gr_ln_g = (const float*)d_in[14];
    const float* gr_ln_b = (const float*)d_in[15];
    const float* pf_wq   = (const float*)d_in[16];
    const float* pf_bq   = (const float*)d_in[17];
    const float* pf_wn   = (const float*)d_in[18];
    const float* pf_bn   = (const float*)d_in[19];
    const float* pf_a1_w = (const float*)d_in[20];
    const float* pf_a1_b = (const float*)d_in[21];
    const float* pf_a2_w = (const float*)d_in[22];
    const float* pf_a2_b = (const float*)d_in[23];
    const float* pf_ln_g = (const float*)d_in[24];
    const float* pf_ln_b = (const float*)d_in[25];
    const float* fu_gw   = (const float*)d_in[26];
    const float* fu_gb   = (const float*)d_in[27];
    const float* fu_pw   = (const float*)d_in[28];
    const float* fu_pb   = (const float*)d_in[29];
    const float* fu_ln_g = (const float*)d_in[30];
    const float* fu_ln_b = (const float*)d_in[31];
    float* out = (float*)d_out;

    float* G = addrf(g_buf);

    static cudaStream_t s1 = nullptr, s2 = nullptr;
    static cudaEvent_t evF = nullptr, evS = nullptr, evE = nullptr, evP = nullptr;
    if (!s1) {
        cudaStreamCreateWithFlags(&s1, cudaStreamNonBlocking);
        cudaStreamCreateWithFlags(&s2, cudaStreamNonBlocking);
        cudaEventCreateWithFlags(&evF, cudaEventDisableTiming);
        cudaEventCreateWithFlags(&evS, cudaEventDisableTiming);
        cudaEventCreateWithFlags(&evE, cudaEventDisableTiming);
        cudaEventCreateWithFlags(&evP, cudaEventDisableTiming);
    }

    // prep on capture stream, then fork edge scan
    k_prep<<<(TOTALF + 255) / 256, 256>>>();
    cudaEventRecord(evF, 0);
    cudaStreamWaitEvent(s2, evF, 0);
    k_edges<<<EE / 256, 256, 0, s2>>>(ei, bidx);
    cudaEventRecord(evE, s2);

    // main chain: projections -> scores
    {
        GPack p;
        p.d[0] = mkdesc(query, HH, gr_wq, HH, 0, gr_bq, G + O_QP,  HH, HH, HH, 0);
        p.d[1] = mkdesc(query, HH, pf_wq, HH, 0, pf_bq, G + O_QP2, HH, HH, HH, 0);
        k_gskm<<<dim3(24, 6, 2), 256>>>(p);
    }
    k_qstats<<<BB, 256>>>(pf_bn);
    {
        GPack p;
        p.d[0] = mkdesc(G + O_QP,  HH, gr_aq_w, HH, 0, gr_aq_b, G + O_Q, HH, HH, HH, 0);
        p.d[1] = mkdesc(G + O_QP2, HH, pf_wn,   HH, 1, nullptr, G + O_T, HH, HH, HH, 0);
        k_gskm<<<dim3(24, 6, 2), 256>>>(p);
    }
    {
        GPack p;
        for (int h = 0; h < NH; h++)
            p.d[h] = mkdesc(G + O_Q + h * DHH, HH, gr_ak_w + h * DHH, HH, 1, nullptr,
                            G + O_U + h * HH, NH * HH, HH, DHH, 0);
        k_gskm<<<dim3(24, 1, 8), 256>>>(p);
    }
    k_scores<<<512, 256>>>(X);
    cudaEventRecord(evS, 0);

    // s1: path branch (overlaps the attention rest)
    cudaStreamWaitEvent(s1, evS, 0);
    k_topnum<<<BB, 256, 0, s1>>>();
    k_recheck48<<<dim3(BB, 3, 6), 256, 0, s1>>>(X, pf_wn, pf_bn);
    cudaStreamWaitEvent(s1, evE, 0);
    k_pathfeat<<<BB, 256, 0, s1>>>(X, ei);
    {
        GPack p;
        p.d[0] = mkdesc(G + O_MEANP, HH, pf_a1_w, HH, 0, pf_a1_b, G + O_AGG1, HH, HH, HH, 0);
        k_gskm<<<dim3(24, 6, 1), 256, 0, s1>>>(p);
    }
    {
        GPack p;
        p.d[0] = mkdesc(G + O_AGG1, HH, pf_a2_w, HH, 0, pf_a2_b, G + O_AGG, HH, HH, HH, 1);
        k_gskm<<<dim3(24, 6, 1), 256, 0, s1>>>(p);
    }
    cudaEventRecord(evP, s1);

    // main: attention rest
    k_smstats<<<BB * NH, 256>>>();
    k_wsum<<<dim3(BB, 16), 192>>>(X);
    {
        GPack p;
        for (int h = 0; h < NH; h++)
            p.d[h] = mkdesc(G + O_WSUM + h * HH, NH * HH, gr_av_w + h * DHH, HH, 0,
                            gr_av_b + h * DHH, G + O_CTX + h * DHH, HH, DHH, HH, 0);
        k_gskm<<<dim3(3, 6, 8), 256>>>(p);
    }
    {
        GPack p;
        p.d[0] = mkdesc(G + O_CTX, HH, gr_ao_w, HH, 0, gr_ao_b, G + O_TMP1, HH, HH, HH, 0);
        p.d[1] = mkdesc(G + O_MEANX, HH, pf_wn, HH, 0, pf_bn, G + O_BMEAN, HH, HH, HH, 0);
        k_gskm<<<dim3(24, 6, 2), 256>>>(p);
    }
    k_ln<<<BB, 256>>>(G + O_TMP1, nullptr, 0, gr_ln_g, gr_ln_b, G + O_GRAPH);

    // join: path-LN needs AGG (s1) + BMEAN + cnt
    cudaStreamWaitEvent(0, evP, 0);
    k_ln<<<BB, 256>>>(G + O_AGG, G + O_BMEAN, 3, pf_ln_g, pf_ln_b, G + O_PATH);

    // fusion
    k_comb<<<BB * 3 * HH / 256, 256>>>(query);
    {
        GPack p;
        p.d[0] = mkdesc(G + O_COMB, 3 * HH, fu_gw, HH, 0, fu_gb, G + O_GATE,  HH, HH, 3 * HH, 0);
        p.d[1] = mkdesc(G + O_COMB, 3 * HH, fu_pw, HH, 0, fu_pb, G + O_FUSED, HH, HH, 3 * HH, 0);
        k_gskm<<<dim3(24, 18, 2), 256>>>(p);
    }
    k_ln<<<BB, 256>>>(G + O_FUSED, G + O_GATE, 2, fu_ln_g, fu_ln_b, out);
}